// round 3
// baseline (speedup 1.0000x reference)
#include <cuda_runtime.h>
#include <cuda_bf16.h>
#include <cstdint>

#define NN 20000
#define EE 1280000
#define CC 256

// ---------------- device scratch (no allocations allowed) ----------------
__device__ __align__(16) float g_xw[(size_t)NN * CC];   // x @ W1_l^T
__device__ __align__(16) float g_xr[(size_t)NN * CC];   // x @ W1_r^T + b1
__device__ int   g_cnt[NN];               // in-degree
__device__ int   g_off[NN];               // CSR offsets (exclusive scan)
__device__ int   g_cur[NN];               // scatter cursors
__device__ int   g_srclist[EE];           // CSR: src node per incoming edge
__device__ float g_s[NN];                 // h1 . W2_l
__device__ float g_t[NN];                 // h1 . W2_r
__device__ float g_part[256];

__device__ __forceinline__ int clampN(int v) {
    return min(max(v, 0), NN - 1);
}

// ---------------- zero counts ----------------
__global__ void zero_kernel() {
    int t = blockIdx.x * blockDim.x + threadIdx.x;
    if (t < NN) g_cnt[t] = 0;
}

// ---------------- in-degree histogram (edge_index is int32!) ------------
__global__ void hist_kernel(const int* __restrict__ ei) {
    int e = blockIdx.x * blockDim.x + threadIdx.x;
    if (e < EE) atomicAdd(&g_cnt[clampN(ei[EE + e])], 1);
}

// ---------------- single-block exclusive scan of g_cnt -> g_off, g_cur ----
__global__ void scan_kernel() {
    __shared__ int sh[1024];
    __shared__ int run_s;
    int t = threadIdx.x;
    if (t == 0) run_s = 0;
    __syncthreads();
    for (int base = 0; base < NN; base += 1024) {
        int v = (base + t < NN) ? g_cnt[base + t] : 0;
        sh[t] = v;
        __syncthreads();
        #pragma unroll
        for (int o = 1; o < 1024; o <<= 1) {
            int x = sh[t];
            int y = (t >= o) ? sh[t - o] : 0;
            __syncthreads();
            sh[t] = x + y;
            __syncthreads();
        }
        int run = run_s;
        int excl = sh[t] - v;
        if (base + t < NN) {
            g_off[base + t] = run + excl;
            g_cur[base + t] = run + excl;
        }
        int total = sh[1023];
        __syncthreads();
        if (t == 0) run_s = run + total;
        __syncthreads();
    }
}

// ---------------- scatter edges into CSR ----------------
__global__ void scatter_kernel(const int* __restrict__ ei) {
    int e = blockIdx.x * blockDim.x + threadIdx.x;
    if (e < EE) {
        int src = clampN(ei[e]);
        int dst = clampN(ei[EE + e]);
        int pos = atomicAdd(&g_cur[dst], 1);
        if (pos >= 0 && pos < EE) g_srclist[pos] = src;
    }
}

// ---------------- fused SGEMM: [20000,256] x [512,256]^T ----------------
#define BM 128
#define BN 128
#define BK 16

__global__ __launch_bounds__(256, 2) void sgemm_kernel(
    const float* __restrict__ x, const float* __restrict__ Wl,
    const float* __restrict__ Wr, const float* __restrict__ b1)
{
    __shared__ float As[BK][BM + 4];
    __shared__ float Bs[BK][BN + 4];
    const int row0 = blockIdx.x * BM;
    const int col0 = blockIdx.y * BN;  // j in [0, 512)
    const int tid = threadIdx.x;
    const int tx = tid & 15;
    const int ty = tid >> 4;
    float acc[8][8] = {};

    for (int k0 = 0; k0 < CC; k0 += BK) {
        #pragma unroll
        for (int i = 0; i < 2; i++) {
            int idx = tid + i * 256;
            int r = idx >> 2;
            int kq = (idx & 3) * 4;
            int gr = row0 + r;
            float4 v = make_float4(0.f, 0.f, 0.f, 0.f);
            if (gr < NN) v = *(const float4*)(x + (size_t)gr * CC + k0 + kq);
            As[kq + 0][r] = v.x; As[kq + 1][r] = v.y;
            As[kq + 2][r] = v.z; As[kq + 3][r] = v.w;
        }
        #pragma unroll
        for (int i = 0; i < 2; i++) {
            int idx = tid + i * 256;
            int r = idx >> 2;
            int kq = (idx & 3) * 4;
            int gj = col0 + r;
            const float* W = (gj < 256) ? (Wl + (size_t)gj * CC)
                                        : (Wr + (size_t)(gj - 256) * CC);
            float4 v = *(const float4*)(W + k0 + kq);
            Bs[kq + 0][r] = v.x; Bs[kq + 1][r] = v.y;
            Bs[kq + 2][r] = v.z; Bs[kq + 3][r] = v.w;
        }
        __syncthreads();
        #pragma unroll
        for (int kk = 0; kk < BK; kk++) {
            float a[8], b[8];
            #pragma unroll
            for (int i = 0; i < 8; i++) a[i] = As[kk][ty * 8 + i];
            #pragma unroll
            for (int i = 0; i < 8; i++) b[i] = Bs[kk][tx * 8 + i];
            #pragma unroll
            for (int i = 0; i < 8; i++)
                #pragma unroll
                for (int j = 0; j < 8; j++)
                    acc[i][j] = fmaf(a[i], b[j], acc[i][j]);
        }
        __syncthreads();
    }

    #pragma unroll
    for (int i = 0; i < 8; i++) {
        int gm = row0 + ty * 8 + i;
        if (gm >= NN) continue;
        #pragma unroll
        for (int j = 0; j < 8; j++) {
            int gj = col0 + tx * 8 + j;
            float vv = acc[i][j];
            if (gj < 256) {
                g_xw[(size_t)gm * CC + gj] = vv;
            } else {
                g_xr[(size_t)gm * CC + (gj - 256)] = vv + b1[gj - 256];
            }
        }
    }
}

// ---- fused: CSR gather of xw + layer-1 epilogue + rank-1 layer-2 proj ----
// One warp per node. Accumulate 256-wide in registers (8 floats/lane),
// then h1 = relu(inv*agg + xr); s = h1.W2l; t = h1.W2r (warp reduce).
__global__ __launch_bounds__(256) void agg_st_kernel(const float* __restrict__ W2l,
                                                     const float* __restrict__ W2r)
{
    int n = (int)(((size_t)blockIdx.x * blockDim.x + threadIdx.x) >> 5);
    int lane = threadIdx.x & 31;
    if (n >= NN) return;
    int off = g_off[n];
    int cnt = g_cnt[n];

    float4 a0 = make_float4(0.f, 0.f, 0.f, 0.f);
    float4 a1 = make_float4(0.f, 0.f, 0.f, 0.f);

    int i = 0;
    for (; i + 4 <= cnt; i += 4) {
        int s0 = g_srclist[off + i + 0];
        int s1 = g_srclist[off + i + 1];
        int s2 = g_srclist[off + i + 2];
        int s3 = g_srclist[off + i + 3];
        const float4* p0 = (const float4*)(g_xw + (size_t)s0 * CC);
        const float4* p1 = (const float4*)(g_xw + (size_t)s1 * CC);
        const float4* p2 = (const float4*)(g_xw + (size_t)s2 * CC);
        const float4* p3 = (const float4*)(g_xw + (size_t)s3 * CC);
        float4 v00 = p0[lane], v01 = p0[lane + 32];
        float4 v10 = p1[lane], v11 = p1[lane + 32];
        float4 v20 = p2[lane], v21 = p2[lane + 32];
        float4 v30 = p3[lane], v31 = p3[lane + 32];
        a0.x += v00.x + v10.x + v20.x + v30.x;
        a0.y += v00.y + v10.y + v20.y + v30.y;
        a0.z += v00.z + v10.z + v20.z + v30.z;
        a0.w += v00.w + v10.w + v20.w + v30.w;
        a1.x += v01.x + v11.x + v21.x + v31.x;
        a1.y += v01.y + v11.y + v21.y + v31.y;
        a1.z += v01.z + v11.z + v21.z + v31.z;
        a1.w += v01.w + v11.w + v21.w + v31.w;
    }
    for (; i < cnt; i++) {
        int s0 = g_srclist[off + i];
        const float4* p0 = (const float4*)(g_xw + (size_t)s0 * CC);
        float4 v0 = p0[lane], v1 = p0[lane + 32];
        a0.x += v0.x; a0.y += v0.y; a0.z += v0.z; a0.w += v0.w;
        a1.x += v1.x; a1.y += v1.y; a1.z += v1.z; a1.w += v1.w;
    }

    float inv = 1.0f / fmaxf((float)cnt, 1.0f);
    const float4* xr = (const float4*)(g_xr + (size_t)n * CC);
    const float4* U4 = (const float4*)W2l;
    const float4* V4 = (const float4*)W2r;
    float su = 0.f, tv = 0.f;
    {
        float4 R = xr[lane];
        float4 U = __ldg(U4 + lane), V = __ldg(V4 + lane);
        float h;
        h = fmaxf(fmaf(inv, a0.x, R.x), 0.f); su = fmaf(h, U.x, su); tv = fmaf(h, V.x, tv);
        h = fmaxf(fmaf(inv, a0.y, R.y), 0.f); su = fmaf(h, U.y, su); tv = fmaf(h, V.y, tv);
        h = fmaxf(fmaf(inv, a0.z, R.z), 0.f); su = fmaf(h, U.z, su); tv = fmaf(h, V.z, tv);
        h = fmaxf(fmaf(inv, a0.w, R.w), 0.f); su = fmaf(h, U.w, su); tv = fmaf(h, V.w, tv);
        R = xr[lane + 32];
        U = __ldg(U4 + lane + 32); V = __ldg(V4 + lane + 32);
        h = fmaxf(fmaf(inv, a1.x, R.x), 0.f); su = fmaf(h, U.x, su); tv = fmaf(h, V.x, tv);
        h = fmaxf(fmaf(inv, a1.y, R.y), 0.f); su = fmaf(h, U.y, su); tv = fmaf(h, V.y, tv);
        h = fmaxf(fmaf(inv, a1.z, R.z), 0.f); su = fmaf(h, U.z, su); tv = fmaf(h, V.z, tv);
        h = fmaxf(fmaf(inv, a1.w, R.w), 0.f); su = fmaf(h, U.w, su); tv = fmaf(h, V.w, tv);
    }
    #pragma unroll
    for (int o = 16; o > 0; o >>= 1) {
        su += __shfl_down_sync(0xffffffffu, su, o);
        tv += __shfl_down_sync(0xffffffffu, tv, o);
    }
    if (lane == 0) { g_s[n] = su; g_t[n] = tv; }
}

// ---- fused: layer-2 scalar gather + relu + fc dot (two-stage reduce) ----
__global__ void l2final_kernel(const float* __restrict__ fcw,
                               const float* __restrict__ b2)
{
    __shared__ float sdata[256];
    float local = 0.f;
    float bias2 = b2[0];
    for (int n = blockIdx.x * blockDim.x + threadIdx.x; n < NN;
         n += gridDim.x * blockDim.x) {
        int off = g_off[n];
        int cnt = g_cnt[n];
        float sum = 0.f;
        for (int i = 0; i < cnt; i++) sum += g_s[g_srclist[off + i]];
        float inv = 1.0f / fmaxf((float)cnt, 1.0f);
        float h = fmaxf(fmaf(inv, sum, bias2 + g_t[n]), 0.f);
        local = fmaf(h, fcw[n], local);
    }
    sdata[threadIdx.x] = local;
    __syncthreads();
    for (int s = 128; s > 0; s >>= 1) {
        if (threadIdx.x < s) sdata[threadIdx.x] += sdata[threadIdx.x + s];
        __syncthreads();
    }
    if (threadIdx.x == 0) g_part[blockIdx.x] = sdata[0];
}

__global__ void final2_kernel(float* __restrict__ out,
                              const float* __restrict__ fcb, int npart)
{
    __shared__ float sdata[256];
    float v = (threadIdx.x < npart) ? g_part[threadIdx.x] : 0.f;
    sdata[threadIdx.x] = v;
    __syncthreads();
    for (int s = 128; s > 0; s >>= 1) {
        if (threadIdx.x < s) sdata[threadIdx.x] += sdata[threadIdx.x + s];
        __syncthreads();
    }
    if (threadIdx.x == 0) out[0] = sdata[0] + fcb[0];
}

// ---------------- launch ----------------
extern "C" void kernel_launch(void* const* d_in, const int* in_sizes, int n_in,
                              void* d_out, int out_size) {
    const float* x    = (const float*)d_in[0];
    const int*   ei   = (const int*)d_in[1];     // int32! (JAX x64 disabled)
    const float* W1l  = (const float*)d_in[2];
    const float* b1   = (const float*)d_in[3];
    const float* W1r  = (const float*)d_in[4];
    const float* W2l  = (const float*)d_in[5];
    const float* b2   = (const float*)d_in[6];
    const float* W2r  = (const float*)d_in[7];
    const float* fcw  = (const float*)d_in[8];
    const float* fcb  = (const float*)d_in[9];
    float* out = (float*)d_out;

    zero_kernel<<<(NN + 255) / 256, 256>>>();
    hist_kernel<<<(EE + 255) / 256, 256>>>(ei);
    scan_kernel<<<1, 1024>>>();
    scatter_kernel<<<(EE + 255) / 256, 256>>>(ei);

    dim3 gemm_grid((NN + BM - 1) / BM, 512 / BN);
    sgemm_kernel<<<gemm_grid, 256>>>(x, W1l, W1r, b1);

    agg_st_kernel<<<(NN * 32 + 255) / 256, 256>>>(W2l, W2r);

    const int FBLK = 148;
    l2final_kernel<<<FBLK, 256>>>(fcw, b2);
    final2_kernel<<<1, 256>>>(out, fcb, FBLK);
}

// round 5
// speedup vs baseline: 1.2278x; 1.2278x over previous
#include <cuda_runtime.h>
#include <cuda_bf16.h>
#include <cstdint>

#define NN 20000
#define EE 1280000
#define CC 256

// ---------------- device scratch (no allocations allowed) ----------------
__device__ __align__(16) float g_xw[(size_t)NN * CC];   // x @ W1_l^T
__device__ __align__(16) float g_xr[(size_t)NN * CC];   // x @ W1_r^T + b1
__device__ int   g_cnt[NN];
__device__ int   g_off[NN];
__device__ int   g_cur[NN];
__device__ int   g_srclist[EE];
__device__ float g_s[NN];
__device__ float g_t[NN];
__device__ float g_part[256];

__device__ __forceinline__ int clampN(int v) { return min(max(v, 0), NN - 1); }

// ---------------- zero counts ----------------
__global__ void zero_kernel() {
    int t = blockIdx.x * blockDim.x + threadIdx.x;
    if (t < NN) g_cnt[t] = 0;
}

// ---------------- in-degree histogram (edge_index is int32) ------------
__global__ void hist_kernel(const int* __restrict__ ei) {
    int e = blockIdx.x * blockDim.x + threadIdx.x;
    if (e < EE) atomicAdd(&g_cnt[clampN(ei[EE + e])], 1);
}

// ---------------- single-block exclusive scan ----------------
__global__ void scan_kernel() {
    __shared__ int sh[1024];
    __shared__ int run_s;
    int t = threadIdx.x;
    if (t == 0) run_s = 0;
    __syncthreads();
    for (int base = 0; base < NN; base += 1024) {
        int v = (base + t < NN) ? g_cnt[base + t] : 0;
        sh[t] = v;
        __syncthreads();
        #pragma unroll
        for (int o = 1; o < 1024; o <<= 1) {
            int x = sh[t];
            int y = (t >= o) ? sh[t - o] : 0;
            __syncthreads();
            sh[t] = x + y;
            __syncthreads();
        }
        int run = run_s;
        int excl = sh[t] - v;
        if (base + t < NN) { g_off[base + t] = run + excl; g_cur[base + t] = run + excl; }
        int total = sh[1023];
        __syncthreads();
        if (t == 0) run_s = run + total;
        __syncthreads();
    }
}

// ---------------- scatter edges into CSR ----------------
__global__ void scatter_kernel(const int* __restrict__ ei) {
    int e = blockIdx.x * blockDim.x + threadIdx.x;
    if (e < EE) {
        int src = clampN(ei[e]);
        int dst = clampN(ei[EE + e]);
        int pos = atomicAdd(&g_cur[dst], 1);
        if (pos >= 0 && pos < EE) g_srclist[pos] = src;
    }
}

// ========== bf16-split tensor GEMM via mma.sync (legacy HMMA) ============
// D = X[20000,256] @ W[512,256]^T, fp32-grade via 3-term bf16 split:
//   X = Xh + Xl, W = Wh + Wl;  D = Xh*Wh + Xl*Wh + Xh*Wl   (err ~2^-17)
// Block tile 128(M) x 128(N), 8 warps (4x2), warp tile 32x64, K chunk 32.
// SMEM holds MMA fragments directly (fragment-major) -> lds.128 / lds.64.

#define KC 32   // k per chunk
#define KS 2    // k-steps (m16n8k16) per chunk

// frag-major sizes (bytes)
#define A_FRAG_BYTES (8 * KS * 32 * 4 * 4)   // 8 m-subtiles
#define B_FRAG_BYTES (16 * KS * 32 * 2 * 4)  // 16 n-subtiles

struct SmemGemm {
    uint32_t AH[A_FRAG_BYTES / 4];
    uint32_t AL[A_FRAG_BYTES / 4];
    uint32_t BH[B_FRAG_BYTES / 4];
    uint32_t BL[B_FRAG_BYTES / 4];
};

__device__ __forceinline__ void bf16_split_pair(float a, float b, uint32_t& hi, uint32_t& lo) {
    __nv_bfloat16 ah = __float2bfloat16_rn(a);
    __nv_bfloat16 bh = __float2bfloat16_rn(b);
    __nv_bfloat16 al = __float2bfloat16_rn(a - __bfloat162float(ah));
    __nv_bfloat16 bl = __float2bfloat16_rn(b - __bfloat162float(bh));
    hi = ((uint32_t)__bfloat16_as_ushort(bh) << 16) | __bfloat16_as_ushort(ah);
    lo = ((uint32_t)__bfloat16_as_ushort(bl) << 16) | __bfloat16_as_ushort(al);
}

#define MMA_BF16(d, a, b) \
    asm volatile("mma.sync.aligned.m16n8k16.row.col.f32.bf16.bf16.f32 " \
                 "{%0,%1,%2,%3}, {%4,%5,%6,%7}, {%8,%9}, {%0,%1,%2,%3};" \
                 : "+f"((d)[0]), "+f"((d)[1]), "+f"((d)[2]), "+f"((d)[3]) \
                 : "r"((a).x), "r"((a).y), "r"((a).z), "r"((a).w), \
                   "r"((b).x), "r"((b).y))

__global__ __launch_bounds__(256, 2) void gemm_mma_kernel(
    const float* __restrict__ x, const float* __restrict__ Wl,
    const float* __restrict__ Wr, const float* __restrict__ b1)
{
    __shared__ SmemGemm sm;
    const int tid = threadIdx.x;
    const int wid = tid >> 5;
    const int lane = tid & 31;
    const int wr = wid >> 1;        // warp row 0..3
    const int wc = wid & 1;         // warp col 0..1
    const int m0 = blockIdx.x * 128;
    const int j0 = blockIdx.y * 128;

    // producer mapping: thread -> (row 0..127, half 0..1)
    const int prow = tid >> 1;
    const int phalf = tid & 1;      // = ks
    const int rr = prow & 15;
    const int msub = prow >> 4;     // A m-subtile
    const int nsub = prow >> 3;     // B n-subtile
    const int nn = prow & 7;

    const int garow = m0 + prow;
    const bool avalid = (garow < NN);
    const float4* xa = (const float4*)(x + (size_t)min(garow, NN - 1) * CC + phalf * 16);
    const int gj = j0 + prow;
    const float* Wsrc = (gj < 256) ? (Wl + (size_t)gj * CC) : (Wr + (size_t)(gj - 256) * CC);
    const float4* wa = (const float4*)(Wsrc + phalf * 16);

    float acc[2][8][4];
    #pragma unroll
    for (int mi = 0; mi < 2; mi++)
        #pragma unroll
        for (int ni = 0; ni < 8; ni++)
            #pragma unroll
            for (int q = 0; q < 4; q++) acc[mi][ni][q] = 0.f;

    for (int kc = 0; kc < CC / KC; kc++) {
        // ---- produce fragments for this K chunk ----
        #pragma unroll
        for (int i = 0; i < 4; i++) {
            float4 av = avalid ? xa[kc * 8 + i] : make_float4(0.f, 0.f, 0.f, 0.f);
            float4 wv = wa[kc * 8 + i];
            #pragma unroll
            for (int p = 0; p < 2; p++) {
                int kk = i * 4 + p * 2;     // 0..14 even
                float a0 = p ? av.z : av.x, a1 = p ? av.w : av.y;
                float w0 = p ? wv.z : wv.x, w1 = p ? wv.w : wv.y;
                uint32_t ahi, alo, whi, wlo;
                bf16_split_pair(a0, a1, ahi, alo);
                bf16_split_pair(w0, w1, whi, wlo);
                // A frag slot
                int alane = (rr & 7) * 4 + ((kk & 7) >> 1);
                int aslot = (rr >> 3) + ((kk >> 3) << 1);
                int aoff = (((msub * KS + phalf) * 32 + alane) << 2) + aslot;
                sm.AH[aoff] = ahi; sm.AL[aoff] = alo;
                // B frag slot
                int blane = nn * 4 + ((kk & 7) >> 1);
                int bslot = kk >> 3;
                int boff = (((nsub * KS + phalf) * 32 + blane) << 1) + bslot;
                sm.BH[boff] = whi; sm.BL[boff] = wlo;
            }
        }
        __syncthreads();
        // ---- consume: 2 k-steps x 8 n x 2 m x 3 split terms ----
        #pragma unroll
        for (int ks = 0; ks < KS; ks++) {
            uint4 Ah[2], Al[2];
            #pragma unroll
            for (int mi = 0; mi < 2; mi++) {
                int ms = wr * 2 + mi;
                int off = ((ms * KS + ks) * 32 + lane) << 2;
                Ah[mi] = *(const uint4*)&sm.AH[off];
                Al[mi] = *(const uint4*)&sm.AL[off];
            }
            #pragma unroll
            for (int ni = 0; ni < 8; ni++) {
                int ns = wc * 8 + ni;
                int boff = ((ns * KS + ks) * 32 + lane) << 1;
                uint2 Bh = *(const uint2*)&sm.BH[boff];
                uint2 Bl = *(const uint2*)&sm.BL[boff];
                #pragma unroll
                for (int mi = 0; mi < 2; mi++) {
                    MMA_BF16(acc[mi][ni], Ah[mi], Bh);
                    MMA_BF16(acc[mi][ni], Al[mi], Bh);
                    MMA_BF16(acc[mi][ni], Ah[mi], Bl);
                }
            }
        }
        __syncthreads();
    }

    // ---- epilogue ----
    const bool to_xw = (j0 < 256);
    #pragma unroll
    for (int mi = 0; mi < 2; mi++) {
        int r0 = m0 + wr * 32 + mi * 16 + (lane >> 2);
        #pragma unroll
        for (int ni = 0; ni < 8; ni++) {
            int col = j0 + wc * 64 + ni * 8 + (lane & 3) * 2;
            if (to_xw) {
                if (r0 < NN)
                    *(float2*)(g_xw + (size_t)r0 * CC + col) = make_float2(acc[mi][ni][0], acc[mi][ni][1]);
                if (r0 + 8 < NN)
                    *(float2*)(g_xw + (size_t)(r0 + 8) * CC + col) = make_float2(acc[mi][ni][2], acc[mi][ni][3]);
            } else {
                int jj = col - 256;
                float2 bv = *(const float2*)(b1 + jj);
                if (r0 < NN)
                    *(float2*)(g_xr + (size_t)r0 * CC + jj) =
                        make_float2(acc[mi][ni][0] + bv.x, acc[mi][ni][1] + bv.y);
                if (r0 + 8 < NN)
                    *(float2*)(g_xr + (size_t)(r0 + 8) * CC + jj) =
                        make_float2(acc[mi][ni][2] + bv.x, acc[mi][ni][3] + bv.y);
            }
        }
    }
}

// ---- fused: CSR gather of xw + layer-1 epilogue + rank-1 layer-2 proj ----
__global__ __launch_bounds__(256) void agg_st_kernel(const float* __restrict__ W2l,
                                                     const float* __restrict__ W2r)
{
    int n = (int)(((size_t)blockIdx.x * blockDim.x + threadIdx.x) >> 5);
    int lane = threadIdx.x & 31;
    if (n >= NN) return;
    int off = g_off[n];
    int cnt = g_cnt[n];

    float4 a0 = make_float4(0.f, 0.f, 0.f, 0.f);
    float4 a1 = make_float4(0.f, 0.f, 0.f, 0.f);

    int i = 0;
    for (; i + 4 <= cnt; i += 4) {
        int s0 = g_srclist[off + i + 0];
        int s1 = g_srclist[off + i + 1];
        int s2 = g_srclist[off + i + 2];
        int s3 = g_srclist[off + i + 3];
        const float4* p0 = (const float4*)(g_xw + (size_t)s0 * CC);
        const float4* p1 = (const float4*)(g_xw + (size_t)s1 * CC);
        const float4* p2 = (const float4*)(g_xw + (size_t)s2 * CC);
        const float4* p3 = (const float4*)(g_xw + (size_t)s3 * CC);
        float4 v00 = p0[lane], v01 = p0[lane + 32];
        float4 v10 = p1[lane], v11 = p1[lane + 32];
        float4 v20 = p2[lane], v21 = p2[lane + 32];
        float4 v30 = p3[lane], v31 = p3[lane + 32];
        a0.x += v00.x + v10.x + v20.x + v30.x;
        a0.y += v00.y + v10.y + v20.y + v30.y;
        a0.z += v00.z + v10.z + v20.z + v30.z;
        a0.w += v00.w + v10.w + v20.w + v30.w;
        a1.x += v01.x + v11.x + v21.x + v31.x;
        a1.y += v01.y + v11.y + v21.y + v31.y;
        a1.z += v01.z + v11.z + v21.z + v31.z;
        a1.w += v01.w + v11.w + v21.w + v31.w;
    }
    for (; i < cnt; i++) {
        int s0 = g_srclist[off + i];
        const float4* p0 = (const float4*)(g_xw + (size_t)s0 * CC);
        float4 v0 = p0[lane], v1 = p0[lane + 32];
        a0.x += v0.x; a0.y += v0.y; a0.z += v0.z; a0.w += v0.w;
        a1.x += v1.x; a1.y += v1.y; a1.z += v1.z; a1.w += v1.w;
    }

    float inv = 1.0f / fmaxf((float)cnt, 1.0f);
    const float4* xr = (const float4*)(g_xr + (size_t)n * CC);
    const float4* U4 = (const float4*)W2l;
    const float4* V4 = (const float4*)W2r;
    float su = 0.f, tv = 0.f;
    {
        float4 R = xr[lane];
        float4 U = __ldg(U4 + lane), V = __ldg(V4 + lane);
        float h;
        h = fmaxf(fmaf(inv, a0.x, R.x), 0.f); su = fmaf(h, U.x, su); tv = fmaf(h, V.x, tv);
        h = fmaxf(fmaf(inv, a0.y, R.y), 0.f); su = fmaf(h, U.y, su); tv = fmaf(h, V.y, tv);
        h = fmaxf(fmaf(inv, a0.z, R.z), 0.f); su = fmaf(h, U.z, su); tv = fmaf(h, V.z, tv);
        h = fmaxf(fmaf(inv, a0.w, R.w), 0.f); su = fmaf(h, U.w, su); tv = fmaf(h, V.w, tv);
        R = xr[lane + 32];
        U = __ldg(U4 + lane + 32); V = __ldg(V4 + lane + 32);
        h = fmaxf(fmaf(inv, a1.x, R.x), 0.f); su = fmaf(h, U.x, su); tv = fmaf(h, V.x, tv);
        h = fmaxf(fmaf(inv, a1.y, R.y), 0.f); su = fmaf(h, U.y, su); tv = fmaf(h, V.y, tv);
        h = fmaxf(fmaf(inv, a1.z, R.z), 0.f); su = fmaf(h, U.z, su); tv = fmaf(h, V.z, tv);
        h = fmaxf(fmaf(inv, a1.w, R.w), 0.f); su = fmaf(h, U.w, su); tv = fmaf(h, V.w, tv);
    }
    #pragma unroll
    for (int o = 16; o > 0; o >>= 1) {
        su += __shfl_down_sync(0xffffffffu, su, o);
        tv += __shfl_down_sync(0xffffffffu, tv, o);
    }
    if (lane == 0) { g_s[n] = su; g_t[n] = tv; }
}

// ---- fused: layer-2 scalar gather + relu + fc dot ----
__global__ void l2final_kernel(const float* __restrict__ fcw,
                               const float* __restrict__ b2)
{
    __shared__ float sdata[256];
    float local = 0.f;
    float bias2 = b2[0];
    for (int n = blockIdx.x * blockDim.x + threadIdx.x; n < NN;
         n += gridDim.x * blockDim.x) {
        int off = g_off[n];
        int cnt = g_cnt[n];
        float sum = 0.f;
        for (int i = 0; i < cnt; i++) sum += g_s[g_srclist[off + i]];
        float inv = 1.0f / fmaxf((float)cnt, 1.0f);
        float h = fmaxf(fmaf(inv, sum, bias2 + g_t[n]), 0.f);
        local = fmaf(h, fcw[n], local);
    }
    sdata[threadIdx.x] = local;
    __syncthreads();
    for (int s = 128; s > 0; s >>= 1) {
        if (threadIdx.x < s) sdata[threadIdx.x] += sdata[threadIdx.x + s];
        __syncthreads();
    }
    if (threadIdx.x == 0) g_part[blockIdx.x] = sdata[0];
}

__global__ void final2_kernel(float* __restrict__ out,
                              const float* __restrict__ fcb, int npart)
{
    __shared__ float sdata[256];
    float v = (threadIdx.x < npart) ? g_part[threadIdx.x] : 0.f;
    sdata[threadIdx.x] = v;
    __syncthreads();
    for (int s = 128; s > 0; s >>= 1) {
        if (threadIdx.x < s) sdata[threadIdx.x] += sdata[threadIdx.x + s];
        __syncthreads();
    }
    if (threadIdx.x == 0) out[0] = sdata[0] + fcb[0];
}

// ---------------- launch ----------------
extern "C" void kernel_launch(void* const* d_in, const int* in_sizes, int n_in,
                              void* d_out, int out_size) {
    const float* x    = (const float*)d_in[0];
    const int*   ei   = (const int*)d_in[1];     // int32 (JAX x64 disabled)
    const float* W1l  = (const float*)d_in[2];
    const float* b1   = (const float*)d_in[3];
    const float* W1r  = (const float*)d_in[4];
    const float* W2l  = (const float*)d_in[5];
    const float* b2   = (const float*)d_in[6];
    const float* W2r  = (const float*)d_in[7];
    const float* fcw  = (const float*)d_in[8];
    const float* fcb  = (const float*)d_in[9];
    float* out = (float*)d_out;

    zero_kernel<<<(NN + 255) / 256, 256>>>();
    hist_kernel<<<(EE + 255) / 256, 256>>>(ei);
    scan_kernel<<<1, 1024>>>();
    scatter_kernel<<<(EE + 255) / 256, 256>>>(ei);

    dim3 gemm_grid((NN + 127) / 128, 4);
    gemm_mma_kernel<<<gemm_grid, 256>>>(x, W1l, W1r, b1);

    agg_st_kernel<<<(NN * 32 + 255) / 256, 256>>>(W2l, W2r);

    const int FBLK = 148;
    l2final_kernel<<<FBLK, 256>>>(fcw, b2);
    final2_kernel<<<1, 256>>>(out, fcb, FBLK);
}

// round 6
// speedup vs baseline: 1.4583x; 1.1877x over previous
#include <cuda_runtime.h>
#include <cuda_bf16.h>
#include <cstdint>

#define NN 20000
#define EE 1280000
#define CC 256

// ---------------- device scratch (no allocations allowed) ----------------
__device__ __align__(16) uint32_t g_xwh[(size_t)NN * 128]; // x@W1_l^T as bf16x2 (col pairs)
__device__ __align__(16) float    g_xr[(size_t)NN * CC];   // x@W1_r^T + b1 (fp32)
__device__ int   g_cnt[NN];
__device__ int   g_off[NN];
__device__ int   g_cur[NN];
__device__ int   g_srclist[EE];
__device__ float g_s[NN];
__device__ float g_t[NN];
__device__ float g_part[256];

__device__ __forceinline__ int clampN(int v) { return min(max(v, 0), NN - 1); }

// ---------------- zero counts ----------------
__global__ void zero_kernel() {
    int t = blockIdx.x * blockDim.x + threadIdx.x;
    if (t < NN) g_cnt[t] = 0;
}

// ---------------- in-degree histogram: 4 edges/thread (int4) -----------
__global__ void hist_kernel(const int* __restrict__ ei) {
    int e4 = (blockIdx.x * blockDim.x + threadIdx.x) * 4;
    if (e4 < EE) {
        int4 d = *(const int4*)(ei + EE + e4);
        atomicAdd(&g_cnt[clampN(d.x)], 1);
        atomicAdd(&g_cnt[clampN(d.y)], 1);
        atomicAdd(&g_cnt[clampN(d.z)], 1);
        atomicAdd(&g_cnt[clampN(d.w)], 1);
    }
}

// ---------------- single-block exclusive scan (shfl-based) -------------
__global__ void scan_kernel() {
    __shared__ int wsum[32];
    int t = threadIdx.x;
    int lane = t & 31;
    int wid = t >> 5;
    int run = 0;
    for (int base = 0; base < NN; base += 1024) {
        int v = (base + t < NN) ? g_cnt[base + t] : 0;
        // warp inclusive scan
        int inc = v;
        #pragma unroll
        for (int o = 1; o < 32; o <<= 1) {
            int y = __shfl_up_sync(0xffffffffu, inc, o);
            if (lane >= o) inc += y;
        }
        if (lane == 31) wsum[wid] = inc;
        __syncthreads();
        if (wid == 0) {
            int w = wsum[lane];
            int wi = w;
            #pragma unroll
            for (int o = 1; o < 32; o <<= 1) {
                int y = __shfl_up_sync(0xffffffffu, wi, o);
                if (lane >= o) wi += y;
            }
            wsum[lane] = wi - w;   // exclusive warp prefix
        }
        __syncthreads();
        int excl = run + wsum[wid] + inc - v;
        if (base + t < NN) { g_off[base + t] = excl; g_cur[base + t] = excl; }
        __syncthreads();
        if (wid == 31 && lane == 31) wsum[0] = excl + v;  // block total end
        __syncthreads();
        run = wsum[0];
        __syncthreads();
    }
}

// ---------------- scatter edges into CSR: 4 edges/thread ---------------
__global__ void scatter_kernel(const int* __restrict__ ei) {
    int e4 = (blockIdx.x * blockDim.x + threadIdx.x) * 4;
    if (e4 < EE) {
        int4 s = *(const int4*)(ei + e4);
        int4 d = *(const int4*)(ei + EE + e4);
        int p0 = atomicAdd(&g_cur[clampN(d.x)], 1);
        int p1 = atomicAdd(&g_cur[clampN(d.y)], 1);
        int p2 = atomicAdd(&g_cur[clampN(d.z)], 1);
        int p3 = atomicAdd(&g_cur[clampN(d.w)], 1);
        if (p0 >= 0 && p0 < EE) g_srclist[p0] = clampN(s.x);
        if (p1 >= 0 && p1 < EE) g_srclist[p1] = clampN(s.y);
        if (p2 >= 0 && p2 < EE) g_srclist[p2] = clampN(s.z);
        if (p3 >= 0 && p3 < EE) g_srclist[p3] = clampN(s.w);
    }
}

// ========== bf16-split tensor GEMM via mma.sync (legacy HMMA) ============
#define KC 32
#define KS 2
#define A_FRAG_BYTES (8 * KS * 32 * 4 * 4)
#define B_FRAG_BYTES (16 * KS * 32 * 2 * 4)

struct SmemGemm {
    uint32_t AH[A_FRAG_BYTES / 4];
    uint32_t AL[A_FRAG_BYTES / 4];
    uint32_t BH[B_FRAG_BYTES / 4];
    uint32_t BL[B_FRAG_BYTES / 4];
};

__device__ __forceinline__ void bf16_split_pair(float a, float b, uint32_t& hi, uint32_t& lo) {
    __nv_bfloat16 ah = __float2bfloat16_rn(a);
    __nv_bfloat16 bh = __float2bfloat16_rn(b);
    __nv_bfloat16 al = __float2bfloat16_rn(a - __bfloat162float(ah));
    __nv_bfloat16 bl = __float2bfloat16_rn(b - __bfloat162float(bh));
    hi = ((uint32_t)__bfloat16_as_ushort(bh) << 16) | __bfloat16_as_ushort(ah);
    lo = ((uint32_t)__bfloat16_as_ushort(bl) << 16) | __bfloat16_as_ushort(al);
}
__device__ __forceinline__ uint32_t pack_bf16x2(float a, float b) {
    __nv_bfloat162 h = __floats2bfloat162_rn(a, b);
    return *(uint32_t*)&h;
}

#define MMA_BF16(d, a, b) \
    asm volatile("mma.sync.aligned.m16n8k16.row.col.f32.bf16.bf16.f32 " \
                 "{%0,%1,%2,%3}, {%4,%5,%6,%7}, {%8,%9}, {%0,%1,%2,%3};" \
                 : "+f"((d)[0]), "+f"((d)[1]), "+f"((d)[2]), "+f"((d)[3]) \
                 : "r"((a).x), "r"((a).y), "r"((a).z), "r"((a).w), \
                   "r"((b).x), "r"((b).y))

__global__ __launch_bounds__(256, 2) void gemm_mma_kernel(
    const float* __restrict__ x, const float* __restrict__ Wl,
    const float* __restrict__ Wr, const float* __restrict__ b1)
{
    __shared__ SmemGemm sm;
    const int tid = threadIdx.x;
    const int wid = tid >> 5;
    const int lane = tid & 31;
    const int wr = wid >> 1;
    const int wc = wid & 1;
    const int m0 = blockIdx.x * 128;
    const int j0 = blockIdx.y * 128;

    const int prow = tid >> 1;
    const int phalf = tid & 1;
    const int rr = prow & 15;
    const int msub = prow >> 4;
    const int nsub = prow >> 3;
    const int nn = prow & 7;

    const int garow = m0 + prow;
    const bool avalid = (garow < NN);
    const float4* xa = (const float4*)(x + (size_t)min(garow, NN - 1) * CC + phalf * 16);
    const int gj = j0 + prow;
    const float* Wsrc = (gj < 256) ? (Wl + (size_t)gj * CC) : (Wr + (size_t)(gj - 256) * CC);
    const float4* wa = (const float4*)(Wsrc + phalf * 16);

    float acc[2][8][4];
    #pragma unroll
    for (int mi = 0; mi < 2; mi++)
        #pragma unroll
        for (int ni = 0; ni < 8; ni++)
            #pragma unroll
            for (int q = 0; q < 4; q++) acc[mi][ni][q] = 0.f;

    for (int kc = 0; kc < CC / KC; kc++) {
        #pragma unroll
        for (int i = 0; i < 4; i++) {
            float4 av = avalid ? xa[kc * 8 + i] : make_float4(0.f, 0.f, 0.f, 0.f);
            float4 wv = wa[kc * 8 + i];
            #pragma unroll
            for (int p = 0; p < 2; p++) {
                int kk = i * 4 + p * 2;
                float a0 = p ? av.z : av.x, a1 = p ? av.w : av.y;
                float w0 = p ? wv.z : wv.x, w1 = p ? wv.w : wv.y;
                uint32_t ahi, alo, whi, wlo;
                bf16_split_pair(a0, a1, ahi, alo);
                bf16_split_pair(w0, w1, whi, wlo);
                int alane = (rr & 7) * 4 + ((kk & 7) >> 1);
                int aslot = (rr >> 3) + ((kk >> 3) << 1);
                int aoff = (((msub * KS + phalf) * 32 + alane) << 2) + aslot;
                sm.AH[aoff] = ahi; sm.AL[aoff] = alo;
                int blane = nn * 4 + ((kk & 7) >> 1);
                int bslot = kk >> 3;
                int boff = (((nsub * KS + phalf) * 32 + blane) << 1) + bslot;
                sm.BH[boff] = whi; sm.BL[boff] = wlo;
            }
        }
        __syncthreads();
        #pragma unroll
        for (int ks = 0; ks < KS; ks++) {
            uint4 Ah[2], Al[2];
            #pragma unroll
            for (int mi = 0; mi < 2; mi++) {
                int ms = wr * 2 + mi;
                int off = ((ms * KS + ks) * 32 + lane) << 2;
                Ah[mi] = *(const uint4*)&sm.AH[off];
                Al[mi] = *(const uint4*)&sm.AL[off];
            }
            #pragma unroll
            for (int ni = 0; ni < 8; ni++) {
                int ns = wc * 8 + ni;
                int boff = ((ns * KS + ks) * 32 + lane) << 1;
                uint2 Bh = *(const uint2*)&sm.BH[boff];
                uint2 Bl = *(const uint2*)&sm.BL[boff];
                #pragma unroll
                for (int mi = 0; mi < 2; mi++) {
                    MMA_BF16(acc[mi][ni], Ah[mi], Bh);
                    MMA_BF16(acc[mi][ni], Al[mi], Bh);
                    MMA_BF16(acc[mi][ni], Ah[mi], Bl);
                }
            }
        }
        __syncthreads();
    }

    const bool to_xw = (j0 < 256);
    #pragma unroll
    for (int mi = 0; mi < 2; mi++) {
        int r0 = m0 + wr * 32 + mi * 16 + (lane >> 2);
        #pragma unroll
        for (int ni = 0; ni < 8; ni++) {
            int col = j0 + wc * 64 + ni * 8 + (lane & 3) * 2;
            if (to_xw) {
                if (r0 < NN)
                    g_xwh[(size_t)r0 * 128 + (col >> 1)] = pack_bf16x2(acc[mi][ni][0], acc[mi][ni][1]);
                if (r0 + 8 < NN)
                    g_xwh[(size_t)(r0 + 8) * 128 + (col >> 1)] = pack_bf16x2(acc[mi][ni][2], acc[mi][ni][3]);
            } else {
                int jj = col - 256;
                float2 bv = *(const float2*)(b1 + jj);
                if (r0 < NN)
                    *(float2*)(g_xr + (size_t)r0 * CC + jj) =
                        make_float2(acc[mi][ni][0] + bv.x, acc[mi][ni][1] + bv.y);
                if (r0 + 8 < NN)
                    *(float2*)(g_xr + (size_t)(r0 + 8) * CC + jj) =
                        make_float2(acc[mi][ni][2] + bv.x, acc[mi][ni][3] + bv.y);
            }
        }
    }
}

// ---- fused: bf16 CSR gather + layer-1 epilogue + rank-1 layer-2 proj ----
// Lane owns cols [lane*4, lane*4+4) and [128+lane*4, 128+lane*4+4).
__global__ __launch_bounds__(256) void agg_st_kernel(const float* __restrict__ W2l,
                                                     const float* __restrict__ W2r)
{
    int n = (int)(((size_t)blockIdx.x * blockDim.x + threadIdx.x) >> 5);
    int lane = threadIdx.x & 31;
    if (n >= NN) return;
    int off = g_off[n];
    int cnt = g_cnt[n];

    float a[8] = {};

    int i = 0;
    for (; i + 2 <= cnt; i += 2) {
        int s0 = g_srclist[off + i + 0];
        int s1 = g_srclist[off + i + 1];
        const uint32_t* b0 = g_xwh + (size_t)s0 * 128;
        const uint32_t* b1p = g_xwh + (size_t)s1 * 128;
        uint2 q00 = *(const uint2*)(b0 + lane * 2);
        uint2 q01 = *(const uint2*)(b0 + 64 + lane * 2);
        uint2 q10 = *(const uint2*)(b1p + lane * 2);
        uint2 q11 = *(const uint2*)(b1p + 64 + lane * 2);
        float2 f;
        f = __bfloat1622float2(*(__nv_bfloat162*)&q00.x); a[0] += f.x; a[1] += f.y;
        f = __bfloat1622float2(*(__nv_bfloat162*)&q00.y); a[2] += f.x; a[3] += f.y;
        f = __bfloat1622float2(*(__nv_bfloat162*)&q01.x); a[4] += f.x; a[5] += f.y;
        f = __bfloat1622float2(*(__nv_bfloat162*)&q01.y); a[6] += f.x; a[7] += f.y;
        f = __bfloat1622float2(*(__nv_bfloat162*)&q10.x); a[0] += f.x; a[1] += f.y;
        f = __bfloat1622float2(*(__nv_bfloat162*)&q10.y); a[2] += f.x; a[3] += f.y;
        f = __bfloat1622float2(*(__nv_bfloat162*)&q11.x); a[4] += f.x; a[5] += f.y;
        f = __bfloat1622float2(*(__nv_bfloat162*)&q11.y); a[6] += f.x; a[7] += f.y;
    }
    for (; i < cnt; i++) {
        int s0 = g_srclist[off + i];
        const uint32_t* b0 = g_xwh + (size_t)s0 * 128;
        uint2 q0 = *(const uint2*)(b0 + lane * 2);
        uint2 q1 = *(const uint2*)(b0 + 64 + lane * 2);
        float2 f;
        f = __bfloat1622float2(*(__nv_bfloat162*)&q0.x); a[0] += f.x; a[1] += f.y;
        f = __bfloat1622float2(*(__nv_bfloat162*)&q0.y); a[2] += f.x; a[3] += f.y;
        f = __bfloat1622float2(*(__nv_bfloat162*)&q1.x); a[4] += f.x; a[5] += f.y;
        f = __bfloat1622float2(*(__nv_bfloat162*)&q1.y); a[6] += f.x; a[7] += f.y;
    }

    float inv = 1.0f / fmaxf((float)cnt, 1.0f);
    float su = 0.f, tv = 0.f;
    {
        float4 R = *(const float4*)(g_xr + (size_t)n * CC + lane * 4);
        float4 U = __ldg((const float4*)(W2l + lane * 4));
        float4 V = __ldg((const float4*)(W2r + lane * 4));
        float h;
        h = fmaxf(fmaf(inv, a[0], R.x), 0.f); su = fmaf(h, U.x, su); tv = fmaf(h, V.x, tv);
        h = fmaxf(fmaf(inv, a[1], R.y), 0.f); su = fmaf(h, U.y, su); tv = fmaf(h, V.y, tv);
        h = fmaxf(fmaf(inv, a[2], R.z), 0.f); su = fmaf(h, U.z, su); tv = fmaf(h, V.z, tv);
        h = fmaxf(fmaf(inv, a[3], R.w), 0.f); su = fmaf(h, U.w, su); tv = fmaf(h, V.w, tv);
        R = *(const float4*)(g_xr + (size_t)n * CC + 128 + lane * 4);
        U = __ldg((const float4*)(W2l + 128 + lane * 4));
        V = __ldg((const float4*)(W2r + 128 + lane * 4));
        h = fmaxf(fmaf(inv, a[4], R.x), 0.f); su = fmaf(h, U.x, su); tv = fmaf(h, V.x, tv);
        h = fmaxf(fmaf(inv, a[5], R.y), 0.f); su = fmaf(h, U.y, su); tv = fmaf(h, V.y, tv);
        h = fmaxf(fmaf(inv, a[6], R.z), 0.f); su = fmaf(h, U.z, su); tv = fmaf(h, V.z, tv);
        h = fmaxf(fmaf(inv, a[7], R.w), 0.f); su = fmaf(h, U.w, su); tv = fmaf(h, V.w, tv);
    }
    #pragma unroll
    for (int o = 16; o > 0; o >>= 1) {
        su += __shfl_down_sync(0xffffffffu, su, o);
        tv += __shfl_down_sync(0xffffffffu, tv, o);
    }
    if (lane == 0) { g_s[n] = su; g_t[n] = tv; }
}

// ---- fused: layer-2 scalar gather + relu + fc dot ----
__global__ void l2final_kernel(const float* __restrict__ fcw,
                               const float* __restrict__ b2)
{
    __shared__ float sdata[256];
    float local = 0.f;
    float bias2 = b2[0];
    for (int n = blockIdx.x * blockDim.x + threadIdx.x; n < NN;
         n += gridDim.x * blockDim.x) {
        int off = g_off[n];
        int cnt = g_cnt[n];
        float sum = 0.f;
        for (int i = 0; i < cnt; i++) sum += g_s[g_srclist[off + i]];
        float inv = 1.0f / fmaxf((float)cnt, 1.0f);
        float h = fmaxf(fmaf(inv, sum, bias2 + g_t[n]), 0.f);
        local = fmaf(h, fcw[n], local);
    }
    sdata[threadIdx.x] = local;
    __syncthreads();
    for (int s = 128; s > 0; s >>= 1) {
        if (threadIdx.x < s) sdata[threadIdx.x] += sdata[threadIdx.x + s];
        __syncthreads();
    }
    if (threadIdx.x == 0) g_part[blockIdx.x] = sdata[0];
}

__global__ void final2_kernel(float* __restrict__ out,
                              const float* __restrict__ fcb, int npart)
{
    __shared__ float sdata[256];
    float v = (threadIdx.x < npart) ? g_part[threadIdx.x] : 0.f;
    sdata[threadIdx.x] = v;
    __syncthreads();
    for (int s = 128; s > 0; s >>= 1) {
        if (threadIdx.x < s) sdata[threadIdx.x] += sdata[threadIdx.x + s];
        __syncthreads();
    }
    if (threadIdx.x == 0) out[0] = sdata[0] + fcb[0];
}

// ---------------- launch ----------------
extern "C" void kernel_launch(void* const* d_in, const int* in_sizes, int n_in,
                              void* d_out, int out_size) {
    const float* x    = (const float*)d_in[0];
    const int*   ei   = (const int*)d_in[1];     // int32 (JAX x64 disabled)
    const float* W1l  = (const float*)d_in[2];
    const float* b1   = (const float*)d_in[3];
    const float* W1r  = (const float*)d_in[4];
    const float* W2l  = (const float*)d_in[5];
    const float* b2   = (const float*)d_in[6];
    const float* W2r  = (const float*)d_in[7];
    const float* fcw  = (const float*)d_in[8];
    const float* fcb  = (const float*)d_in[9];
    float* out = (float*)d_out;

    zero_kernel<<<(NN + 255) / 256, 256>>>();
    hist_kernel<<<(EE / 4 + 255) / 256, 256>>>(ei);
    scan_kernel<<<1, 1024>>>();
    scatter_kernel<<<(EE / 4 + 255) / 256, 256>>>(ei);

    dim3 gemm_grid((NN + 127) / 128, 4);
    gemm_mma_kernel<<<gemm_grid, 256>>>(x, W1l, W1r, b1);

    agg_st_kernel<<<(NN * 32 + 255) / 256, 256>>>(W2l, W2r);

    const int FBLK = 148;
    l2final_kernel<<<FBLK, 256>>>(fcw, b2);
    final2_kernel<<<1, 256>>>(out, fcb, FBLK);
}

// round 7
// speedup vs baseline: 1.5444x; 1.0591x over previous
#include <cuda_runtime.h>
#include <cuda_bf16.h>
#include <cstdint>

#define NN 20000
#define EE 1280000
#define CC 256
#define STR 160   // bucket stride (max degree ~100 at 12 sigma)

// ---------------- device scratch (no allocations allowed) ----------------
__device__ __align__(16) uint32_t g_xwh[(size_t)NN * 128]; // x@W1_l^T bf16x2
__device__ __align__(16) float    g_xr[(size_t)NN * CC];   // x@W1_r^T + b1
__device__ __align__(16) uint32_t g_xh[(size_t)NN * 128];  // x hi split bf16x2
__device__ __align__(16) uint32_t g_xl[(size_t)NN * 128];  // x lo split
__device__ __align__(16) uint32_t g_wh[512 * 128];         // W hi split
__device__ __align__(16) uint32_t g_wl[512 * 128];         // W lo split
__device__ int   g_cnt[NN];
__device__ int   g_bucket[(size_t)NN * STR];
__device__ float g_s[NN];
__device__ float g_t[NN];
__device__ float g_part[256];

__device__ __forceinline__ int clampN(int v) { return min(max(v, 0), NN - 1); }

__device__ __forceinline__ void bf16_split_pair(float a, float b, uint32_t& hi, uint32_t& lo) {
    __nv_bfloat16 ah = __float2bfloat16_rn(a);
    __nv_bfloat16 bh = __float2bfloat16_rn(b);
    __nv_bfloat16 al = __float2bfloat16_rn(a - __bfloat162float(ah));
    __nv_bfloat16 bl = __float2bfloat16_rn(b - __bfloat162float(bh));
    hi = ((uint32_t)__bfloat16_as_ushort(bh) << 16) | __bfloat16_as_ushort(ah);
    lo = ((uint32_t)__bfloat16_as_ushort(bl) << 16) | __bfloat16_as_ushort(al);
}
__device__ __forceinline__ uint32_t pack_bf16x2(float a, float b) {
    __nv_bfloat162 h = __floats2bfloat162_rn(a, b);
    return *(uint32_t*)&h;
}

// ---------------- zero counts ----------------
__global__ void zero_kernel() {
    int t = blockIdx.x * blockDim.x + threadIdx.x;
    if (t < NN) g_cnt[t] = 0;
}

// ====== fused prep: [0,1250) scatter | [1250,6250) x-split | rest W-split ==
#define SCAT_B 1250
#define XC_B 5000
#define WC_B 128

__global__ __launch_bounds__(256) void prep_kernel(
    const int* __restrict__ ei, const float* __restrict__ x,
    const float* __restrict__ Wl, const float* __restrict__ Wr)
{
    int b = blockIdx.x;
    int tid = threadIdx.x;
    if (b < SCAT_B) {
        int e4 = (b * 256 + tid) * 4;
        int4 s = *(const int4*)(ei + e4);
        int4 d = *(const int4*)(ei + EE + e4);
        int d0 = clampN(d.x), d1 = clampN(d.y), d2 = clampN(d.z), d3 = clampN(d.w);
        int p0 = atomicAdd(&g_cnt[d0], 1);
        int p1 = atomicAdd(&g_cnt[d1], 1);
        int p2 = atomicAdd(&g_cnt[d2], 1);
        int p3 = atomicAdd(&g_cnt[d3], 1);
        if (p0 < STR) g_bucket[(size_t)d0 * STR + p0] = clampN(s.x);
        if (p1 < STR) g_bucket[(size_t)d1 * STR + p1] = clampN(s.y);
        if (p2 < STR) g_bucket[(size_t)d2 * STR + p2] = clampN(s.z);
        if (p3 < STR) g_bucket[(size_t)d3 * STR + p3] = clampN(s.w);
    } else if (b < SCAT_B + XC_B) {
        int e = ((b - SCAT_B) * 256 + tid) * 4;       // element idx, multiple of 4
        float4 v = *(const float4*)(x + e);
        uint32_t h0, l0, h1, l1;
        bf16_split_pair(v.x, v.y, h0, l0);
        bf16_split_pair(v.z, v.w, h1, l1);
        int row = e >> 8, kk = e & 255;
        size_t o = (size_t)row * 128 + (kk >> 1);
        *(uint2*)(g_xh + o) = make_uint2(h0, h1);
        *(uint2*)(g_xl + o) = make_uint2(l0, l1);
    } else {
        int e = ((b - SCAT_B - XC_B) * 256 + tid) * 4;  // over 512*256
        int row = e >> 8, kk = e & 255;
        const float* W = (row < 256) ? (Wl + (size_t)row * CC + kk)
                                     : (Wr + (size_t)(row - 256) * CC + kk);
        float4 v = *(const float4*)W;
        uint32_t h0, l0, h1, l1;
        bf16_split_pair(v.x, v.y, h0, l0);
        bf16_split_pair(v.z, v.w, h1, l1);
        size_t o = (size_t)row * 128 + (kk >> 1);
        *(uint2*)(g_wh + o) = make_uint2(h0, h1);
        *(uint2*)(g_wl + o) = make_uint2(l0, l1);
    }
}

// ========== bf16-split tensor GEMM via mma.sync (pre-split inputs) =======
#define KC 32
#define KS 2
#define A_FRAG_U32 (8 * KS * 32 * 4)
#define B_FRAG_U32 (16 * KS * 32 * 2)

struct SmemGemm {
    uint32_t AH[A_FRAG_U32];
    uint32_t AL[A_FRAG_U32];
    uint32_t BH[B_FRAG_U32];
    uint32_t BL[B_FRAG_U32];
};

#define MMA_BF16(d, a, b) \
    asm volatile("mma.sync.aligned.m16n8k16.row.col.f32.bf16.bf16.f32 " \
                 "{%0,%1,%2,%3}, {%4,%5,%6,%7}, {%8,%9}, {%0,%1,%2,%3};" \
                 : "+f"((d)[0]), "+f"((d)[1]), "+f"((d)[2]), "+f"((d)[3]) \
                 : "r"((a).x), "r"((a).y), "r"((a).z), "r"((a).w), \
                   "r"((b).x), "r"((b).y))

__global__ __launch_bounds__(256, 2) void gemm_mma_kernel(const float* __restrict__ b1)
{
    __shared__ SmemGemm sm;
    const int tid = threadIdx.x;
    const int wid = tid >> 5;
    const int lane = tid & 31;
    const int wr = wid >> 1;
    const int wc = wid & 1;
    const int m0 = blockIdx.x * 128;
    const int j0 = blockIdx.y * 128;
    const bool to_xw = (j0 < 256);

    const int prow = tid >> 1;
    const int phalf = tid & 1;
    const int rr = prow & 15;
    const int msub = prow >> 4;
    const int nsub = prow >> 3;
    const int nn = prow & 7;

    const int garow = m0 + prow;
    const bool avalid = (garow < NN);
    const uint4* xh4 = (const uint4*)(g_xh + (size_t)min(garow, NN - 1) * 128);
    const uint4* xl4 = (const uint4*)(g_xl + (size_t)min(garow, NN - 1) * 128);
    const uint4* wh4 = (const uint4*)(g_wh + (size_t)(j0 + prow) * 128);
    const uint4* wl4 = (const uint4*)(g_wl + (size_t)(j0 + prow) * 128);

    float acc[2][8][4];
    #pragma unroll
    for (int mi = 0; mi < 2; mi++)
        #pragma unroll
        for (int ni = 0; ni < 8; ni++)
            #pragma unroll
            for (int q = 0; q < 4; q++) acc[mi][ni][q] = 0.f;

    for (int kc = 0; kc < CC / KC; kc++) {
        // ---- producer: pure relayout, no conversion math ----
        {
            int u = kc * 4 + phalf * 2;   // uint4 index: 8 pairs per (chunk, half)
            uint4 ah0 = xh4[u], ah1 = xh4[u + 1];
            uint4 al0 = xl4[u], al1 = xl4[u + 1];
            if (!avalid) { ah0 = ah1 = al0 = al1 = make_uint4(0, 0, 0, 0); }
            uint4 bh0 = wh4[u], bh1 = wh4[u + 1];
            const uint32_t* ahp = (const uint32_t*)&ah0;   // q=0..3 in ah0, 4..7 in ah1
            const uint32_t* alp = (const uint32_t*)&al0;
            const uint32_t* bhp = (const uint32_t*)&bh0;
            #pragma unroll
            for (int q = 0; q < 8; q++) {
                uint32_t ah = (q < 4) ? ahp[q] : ((const uint32_t*)&ah1)[q - 4];
                uint32_t al = (q < 4) ? alp[q] : ((const uint32_t*)&al1)[q - 4];
                uint32_t bh = (q < 4) ? bhp[q] : ((const uint32_t*)&bh1)[q - 4];
                int alane = (rr & 7) * 4 + (q & 3);
                int aslot = (rr >> 3) + ((q >> 2) << 1);
                int aoff = (((msub * KS + phalf) * 32 + alane) << 2) + aslot;
                sm.AH[aoff] = ah; sm.AL[aoff] = al;
                int blane = nn * 4 + (q & 3);
                int bslot = q >> 2;
                int boff = (((nsub * KS + phalf) * 32 + blane) << 1) + bslot;
                sm.BH[boff] = bh;
            }
            if (!to_xw) {
                uint4 bl0 = wl4[u], bl1 = wl4[u + 1];
                const uint32_t* blp = (const uint32_t*)&bl0;
                #pragma unroll
                for (int q = 0; q < 8; q++) {
                    uint32_t bl = (q < 4) ? blp[q] : ((const uint32_t*)&bl1)[q - 4];
                    int blane = nn * 4 + (q & 3);
                    int bslot = q >> 2;
                    int boff = (((nsub * KS + phalf) * 32 + blane) << 1) + bslot;
                    sm.BL[boff] = bl;
                }
            }
        }
        __syncthreads();
        // ---- consumer ----
        #pragma unroll
        for (int ks = 0; ks < KS; ks++) {
            uint4 Ah[2], Al[2];
            #pragma unroll
            for (int mi = 0; mi < 2; mi++) {
                int ms = wr * 2 + mi;
                int off = ((ms * KS + ks) * 32 + lane) << 2;
                Ah[mi] = *(const uint4*)&sm.AH[off];
                Al[mi] = *(const uint4*)&sm.AL[off];
            }
            #pragma unroll
            for (int ni = 0; ni < 8; ni++) {
                int ns = wc * 8 + ni;
                int boff = ((ns * KS + ks) * 32 + lane) << 1;
                uint2 Bh = *(const uint2*)&sm.BH[boff];
                #pragma unroll
                for (int mi = 0; mi < 2; mi++) {
                    MMA_BF16(acc[mi][ni], Ah[mi], Bh);
                    MMA_BF16(acc[mi][ni], Al[mi], Bh);
                }
                if (!to_xw) {
                    uint2 Bl = *(const uint2*)&sm.BL[boff];
                    #pragma unroll
                    for (int mi = 0; mi < 2; mi++)
                        MMA_BF16(acc[mi][ni], Ah[mi], Bl);
                }
            }
        }
        __syncthreads();
    }

    #pragma unroll
    for (int mi = 0; mi < 2; mi++) {
        int r0 = m0 + wr * 32 + mi * 16 + (lane >> 2);
        #pragma unroll
        for (int ni = 0; ni < 8; ni++) {
            int col = j0 + wc * 64 + ni * 8 + (lane & 3) * 2;
            if (to_xw) {
                if (r0 < NN)
                    g_xwh[(size_t)r0 * 128 + (col >> 1)] = pack_bf16x2(acc[mi][ni][0], acc[mi][ni][1]);
                if (r0 + 8 < NN)
                    g_xwh[(size_t)(r0 + 8) * 128 + (col >> 1)] = pack_bf16x2(acc[mi][ni][2], acc[mi][ni][3]);
            } else {
                int jj = col - 256;
                float2 bv = *(const float2*)(b1 + jj);
                if (r0 < NN)
                    *(float2*)(g_xr + (size_t)r0 * CC + jj) =
                        make_float2(acc[mi][ni][0] + bv.x, acc[mi][ni][1] + bv.y);
                if (r0 + 8 < NN)
                    *(float2*)(g_xr + (size_t)(r0 + 8) * CC + jj) =
                        make_float2(acc[mi][ni][2] + bv.x, acc[mi][ni][3] + bv.y);
            }
        }
    }
}

// ---- fused: bf16 bucket gather + layer-1 epilogue + rank-1 layer-2 proj --
__global__ __launch_bounds__(256) void agg_st_kernel(const float* __restrict__ W2l,
                                                     const float* __restrict__ W2r)
{
    int n = (int)(((size_t)blockIdx.x * blockDim.x + threadIdx.x) >> 5);
    int lane = threadIdx.x & 31;
    if (n >= NN) return;
    const int* lst = g_bucket + (size_t)n * STR;
    int cnt = g_cnt[n];
    int m = min(cnt, STR);

    float a[8] = {};

    int i = 0;
    for (; i + 2 <= m; i += 2) {
        int s0 = lst[i], s1 = lst[i + 1];
        const uint32_t* b0 = g_xwh + (size_t)s0 * 128;
        const uint32_t* b1p = g_xwh + (size_t)s1 * 128;
        uint2 q00 = *(const uint2*)(b0 + lane * 2);
        uint2 q01 = *(const uint2*)(b0 + 64 + lane * 2);
        uint2 q10 = *(const uint2*)(b1p + lane * 2);
        uint2 q11 = *(const uint2*)(b1p + 64 + lane * 2);
        float2 f;
        f = __bfloat1622float2(*(__nv_bfloat162*)&q00.x); a[0] += f.x; a[1] += f.y;
        f = __bfloat1622float2(*(__nv_bfloat162*)&q00.y); a[2] += f.x; a[3] += f.y;
        f = __bfloat1622float2(*(__nv_bfloat162*)&q01.x); a[4] += f.x; a[5] += f.y;
        f = __bfloat1622float2(*(__nv_bfloat162*)&q01.y); a[6] += f.x; a[7] += f.y;
        f = __bfloat1622float2(*(__nv_bfloat162*)&q10.x); a[0] += f.x; a[1] += f.y;
        f = __bfloat1622float2(*(__nv_bfloat162*)&q10.y); a[2] += f.x; a[3] += f.y;
        f = __bfloat1622float2(*(__nv_bfloat162*)&q11.x); a[4] += f.x; a[5] += f.y;
        f = __bfloat1622float2(*(__nv_bfloat162*)&q11.y); a[6] += f.x; a[7] += f.y;
    }
    for (; i < m; i++) {
        int s0 = lst[i];
        const uint32_t* b0 = g_xwh + (size_t)s0 * 128;
        uint2 q0 = *(const uint2*)(b0 + lane * 2);
        uint2 q1 = *(const uint2*)(b0 + 64 + lane * 2);
        float2 f;
        f = __bfloat1622float2(*(__nv_bfloat162*)&q0.x); a[0] += f.x; a[1] += f.y;
        f = __bfloat1622float2(*(__nv_bfloat162*)&q0.y); a[2] += f.x; a[3] += f.y;
        f = __bfloat1622float2(*(__nv_bfloat162*)&q1.x); a[4] += f.x; a[5] += f.y;
        f = __bfloat1622float2(*(__nv_bfloat162*)&q1.y); a[6] += f.x; a[7] += f.y;
    }

    float inv = 1.0f / fmaxf((float)cnt, 1.0f);
    float su = 0.f, tv = 0.f;
    {
        float4 R = *(const float4*)(g_xr + (size_t)n * CC + lane * 4);
        float4 U = __ldg((const float4*)(W2l + lane * 4));
        float4 V = __ldg((const float4*)(W2r + lane * 4));
        float h;
        h = fmaxf(fmaf(inv, a[0], R.x), 0.f); su = fmaf(h, U.x, su); tv = fmaf(h, V.x, tv);
        h = fmaxf(fmaf(inv, a[1], R.y), 0.f); su = fmaf(h, U.y, su); tv = fmaf(h, V.y, tv);
        h = fmaxf(fmaf(inv, a[2], R.z), 0.f); su = fmaf(h, U.z, su); tv = fmaf(h, V.z, tv);
        h = fmaxf(fmaf(inv, a[3], R.w), 0.f); su = fmaf(h, U.w, su); tv = fmaf(h, V.w, tv);
        R = *(const float4*)(g_xr + (size_t)n * CC + 128 + lane * 4);
        U = __ldg((const float4*)(W2l + 128 + lane * 4));
        V = __ldg((const float4*)(W2r + 128 + lane * 4));
        h = fmaxf(fmaf(inv, a[4], R.x), 0.f); su = fmaf(h, U.x, su); tv = fmaf(h, V.x, tv);
        h = fmaxf(fmaf(inv, a[5], R.y), 0.f); su = fmaf(h, U.y, su); tv = fmaf(h, V.y, tv);
        h = fmaxf(fmaf(inv, a[6], R.z), 0.f); su = fmaf(h, U.z, su); tv = fmaf(h, V.z, tv);
        h = fmaxf(fmaf(inv, a[7], R.w), 0.f); su = fmaf(h, U.w, su); tv = fmaf(h, V.w, tv);
    }
    #pragma unroll
    for (int o = 16; o > 0; o >>= 1) {
        su += __shfl_down_sync(0xffffffffu, su, o);
        tv += __shfl_down_sync(0xffffffffu, tv, o);
    }
    if (lane == 0) { g_s[n] = su; g_t[n] = tv; }
}

// ---- fused: layer-2 scalar gather + relu + fc dot ----
__global__ void l2final_kernel(const float* __restrict__ fcw,
                               const float* __restrict__ b2)
{
    __shared__ float sdata[256];
    float local = 0.f;
    float bias2 = b2[0];
    for (int n = blockIdx.x * blockDim.x + threadIdx.x; n < NN;
         n += gridDim.x * blockDim.x) {
        const int* lst = g_bucket + (size_t)n * STR;
        int cnt = g_cnt[n];
        int m = min(cnt, STR);
        float sum = 0.f;
        for (int i = 0; i < m; i++) sum += g_s[lst[i]];
        float inv = 1.0f / fmaxf((float)cnt, 1.0f);
        float h = fmaxf(fmaf(inv, sum, bias2 + g_t[n]), 0.f);
        local = fmaf(h, fcw[n], local);
    }
    sdata[threadIdx.x] = local;
    __syncthreads();
    for (int s = 128; s > 0; s >>= 1) {
        if (threadIdx.x < s) sdata[threadIdx.x] += sdata[threadIdx.x + s];
        __syncthreads();
    }
    if (threadIdx.x == 0) g_part[blockIdx.x] = sdata[0];
}

__global__ void final2_kernel(float* __restrict__ out,
                              const float* __restrict__ fcb, int npart)
{
    __shared__ float sdata[256];
    float v = (threadIdx.x < npart) ? g_part[threadIdx.x] : 0.f;
    sdata[threadIdx.x] = v;
    __syncthreads();
    for (int s = 128; s > 0; s >>= 1) {
        if (threadIdx.x < s) sdata[threadIdx.x] += sdata[threadIdx.x + s];
        __syncthreads();
    }
    if (threadIdx.x == 0) out[0] = sdata[0] + fcb[0];
}

// ---------------- launch ----------------
extern "C" void kernel_launch(void* const* d_in, const int* in_sizes, int n_in,
                              void* d_out, int out_size) {
    const float* x    = (const float*)d_in[0];
    const int*   ei   = (const int*)d_in[1];     // int32 (JAX x64 disabled)
    const float* W1l  = (const float*)d_in[2];
    const float* b1   = (const float*)d_in[3];
    const float* W1r  = (const float*)d_in[4];
    const float* W2l  = (const float*)d_in[5];
    const float* b2   = (const float*)d_in[6];
    const float* W2r  = (const float*)d_in[7];
    const float* fcw  = (const float*)d_in[8];
    const float* fcb  = (const float*)d_in[9];
    float* out = (float*)d_out;

    zero_kernel<<<(NN + 255) / 256, 256>>>();
    prep_kernel<<<SCAT_B + XC_B + WC_B, 256>>>(ei, x, W1l, W1r);

    dim3 gemm_grid((NN + 127) / 128, 4);
    gemm_mma_kernel<<<gemm_grid, 256>>>(b1);

    agg_st_kernel<<<(NN * 32 + 255) / 256, 256>>>(W2l, W2r);

    const int FBLK = 148;
    l2final_kernel<<<FBLK, 256>>>(fcw, b2);
    final2_kernel<<<1, 256>>>(out, fcb, FBLK);
}

// round 9
// speedup vs baseline: 1.7720x; 1.1473x over previous
#include <cuda_runtime.h>
#include <cuda_bf16.h>
#include <cstdint>

#define NN 20000
#define EE 1280000
#define CC 256
#define STR 160   // bucket stride (max degree ~100 at 12 sigma)

// ---------------- device scratch (no allocations allowed) ----------------
__device__ __align__(16) uint32_t g_xwh[(size_t)NN * 128]; // x@W1_l^T bf16x2
__device__ __align__(16) float    g_xr[(size_t)NN * CC];   // x@W1_r^T + b1
__device__ __align__(16) uint32_t g_xh[(size_t)NN * 128];  // x hi split bf16x2
__device__ __align__(16) uint32_t g_xl[(size_t)NN * 128];  // x lo split
__device__ __align__(16) uint32_t g_wh[512 * 128];         // W hi split
__device__ __align__(16) uint32_t g_wl[512 * 128];         // W lo split
__device__ int   g_cnt[NN];
__device__ __align__(16) int g_bucket[(size_t)NN * STR];
__device__ float g_s[NN];
__device__ float g_t[NN];
__device__ float g_part[256];

__device__ __forceinline__ int clampN(int v) { return min(max(v, 0), NN - 1); }

__device__ __forceinline__ void bf16_split_pair(float a, float b, uint32_t& hi, uint32_t& lo) {
    __nv_bfloat16 ah = __float2bfloat16_rn(a);
    __nv_bfloat16 bh = __float2bfloat16_rn(b);
    __nv_bfloat16 al = __float2bfloat16_rn(a - __bfloat162float(ah));
    __nv_bfloat16 bl = __float2bfloat16_rn(b - __bfloat162float(bh));
    hi = ((uint32_t)__bfloat16_as_ushort(bh) << 16) | __bfloat16_as_ushort(ah);
    lo = ((uint32_t)__bfloat16_as_ushort(bl) << 16) | __bfloat16_as_ushort(al);
}
__device__ __forceinline__ uint32_t pack_bf16x2(float a, float b) {
    __nv_bfloat162 h = __floats2bfloat162_rn(a, b);
    return *(uint32_t*)&h;
}

// ---------------- zero counts ----------------
__global__ void zero_kernel() {
    int t = blockIdx.x * blockDim.x + threadIdx.x;
    if (t < NN) g_cnt[t] = 0;
}

// ====== fused prep: scatter (8 edges/thr) | x-split | W-split ============
#define SCAT_B 625
#define XC_B 5000
#define WC_B 128

__global__ __launch_bounds__(256) void prep_kernel(
    const int* __restrict__ ei, const float* __restrict__ x,
    const float* __restrict__ Wl, const float* __restrict__ Wr)
{
    int b = blockIdx.x;
    int tid = threadIdx.x;
    if (b < SCAT_B) {
        int e8 = (b * 256 + tid) * 8;
        #pragma unroll
        for (int h = 0; h < 2; h++) {
            int4 s = *(const int4*)(ei + e8 + h * 4);
            int4 d = *(const int4*)(ei + EE + e8 + h * 4);
            int d0 = clampN(d.x), d1 = clampN(d.y), d2 = clampN(d.z), d3 = clampN(d.w);
            int p0 = atomicAdd(&g_cnt[d0], 1);
            int p1 = atomicAdd(&g_cnt[d1], 1);
            int p2 = atomicAdd(&g_cnt[d2], 1);
            int p3 = atomicAdd(&g_cnt[d3], 1);
            if (p0 < STR) g_bucket[(size_t)d0 * STR + p0] = clampN(s.x);
            if (p1 < STR) g_bucket[(size_t)d1 * STR + p1] = clampN(s.y);
            if (p2 < STR) g_bucket[(size_t)d2 * STR + p2] = clampN(s.z);
            if (p3 < STR) g_bucket[(size_t)d3 * STR + p3] = clampN(s.w);
        }
    } else if (b < SCAT_B + XC_B) {
        int e = ((b - SCAT_B) * 256 + tid) * 4;
        float4 v = *(const float4*)(x + e);
        uint32_t h0, l0, h1, l1;
        bf16_split_pair(v.x, v.y, h0, l0);
        bf16_split_pair(v.z, v.w, h1, l1);
        int row = e >> 8, kk = e & 255;
        size_t o = (size_t)row * 128 + (kk >> 1);
        *(uint2*)(g_xh + o) = make_uint2(h0, h1);
        *(uint2*)(g_xl + o) = make_uint2(l0, l1);
    } else {
        int e = ((b - SCAT_B - XC_B) * 256 + tid) * 4;  // over 512*256
        int row = e >> 8, kk = e & 255;
        const float* W = (row < 256) ? (Wl + (size_t)row * CC + kk)
                                     : (Wr + (size_t)(row - 256) * CC + kk);
        float4 v = *(const float4*)W;
        uint32_t h0, l0, h1, l1;
        bf16_split_pair(v.x, v.y, h0, l0);
        bf16_split_pair(v.z, v.w, h1, l1);
        size_t o = (size_t)row * 128 + (kk >> 1);
        *(uint2*)(g_wh + o) = make_uint2(h0, h1);
        *(uint2*)(g_wl + o) = make_uint2(l0, l1);
    }
}

// ========== bf16 split GEMM via mma.sync =================================
// xw blocks: D = (Ah + Al) * Bh          (2 terms; output bf16 anyway)
// xr blocks: D = (Ah + Al) * Bh + Ah*Bl  (3 terms; fp32-grade)
#define KC 32
#define KS 2
#define A_FRAG_U32 (8 * KS * 32 * 4)
#define B_FRAG_U32 (16 * KS * 32 * 2)

struct SmemGemm {
    uint32_t AH[A_FRAG_U32];
    uint32_t AL[A_FRAG_U32];
    uint32_t BH[B_FRAG_U32];
    uint32_t BL[B_FRAG_U32];
};

#define MMA_BF16(d, a, b) \
    asm volatile("mma.sync.aligned.m16n8k16.row.col.f32.bf16.bf16.f32 " \
                 "{%0,%1,%2,%3}, {%4,%5,%6,%7}, {%8,%9}, {%0,%1,%2,%3};" \
                 : "+f"((d)[0]), "+f"((d)[1]), "+f"((d)[2]), "+f"((d)[3]) \
                 : "r"((a).x), "r"((a).y), "r"((a).z), "r"((a).w), \
                   "r"((b).x), "r"((b).y))

__global__ __launch_bounds__(256, 2) void gemm_mma_kernel(const float* __restrict__ b1)
{
    __shared__ SmemGemm sm;
    const int tid = threadIdx.x;
    const int wid = tid >> 5;
    const int lane = tid & 31;
    const int wr = wid >> 1;
    const int wc = wid & 1;
    const int m0 = blockIdx.x * 128;
    const int j0 = blockIdx.y * 128;
    const bool to_xw = (j0 < 256);

    const int prow = tid >> 1;
    const int phalf = tid & 1;
    const int rr = prow & 15;
    const int msub = prow >> 4;
    const int nsub = prow >> 3;
    const int nn = prow & 7;

    const int garow = m0 + prow;
    const bool avalid = (garow < NN);
    const uint4* xh4 = (const uint4*)(g_xh + (size_t)min(garow, NN - 1) * 128);
    const uint4* xl4 = (const uint4*)(g_xl + (size_t)min(garow, NN - 1) * 128);
    const uint4* wh4 = (const uint4*)(g_wh + (size_t)(j0 + prow) * 128);
    const uint4* wl4 = (const uint4*)(g_wl + (size_t)(j0 + prow) * 128);

    float acc[2][8][4];
    #pragma unroll
    for (int mi = 0; mi < 2; mi++)
        #pragma unroll
        for (int ni = 0; ni < 8; ni++)
            #pragma unroll
            for (int q = 0; q < 4; q++) acc[mi][ni][q] = 0.f;

    for (int kc = 0; kc < CC / KC; kc++) {
        {
            int u = kc * 4 + phalf * 2;
            uint4 ah0 = xh4[u], ah1 = xh4[u + 1];
            uint4 al0 = xl4[u], al1 = xl4[u + 1];
            if (!avalid) { ah0 = ah1 = al0 = al1 = make_uint4(0, 0, 0, 0); }
            uint4 bh0 = wh4[u], bh1 = wh4[u + 1];
            #pragma unroll
            for (int q = 0; q < 8; q++) {
                uint32_t ah = (q < 4) ? ((const uint32_t*)&ah0)[q] : ((const uint32_t*)&ah1)[q - 4];
                uint32_t al = (q < 4) ? ((const uint32_t*)&al0)[q] : ((const uint32_t*)&al1)[q - 4];
                uint32_t bh = (q < 4) ? ((const uint32_t*)&bh0)[q] : ((const uint32_t*)&bh1)[q - 4];
                int alane = (rr & 7) * 4 + (q & 3);
                int aslot = (rr >> 3) + ((q >> 2) << 1);
                int aoff = (((msub * KS + phalf) * 32 + alane) << 2) + aslot;
                sm.AH[aoff] = ah; sm.AL[aoff] = al;
                int blane = nn * 4 + (q & 3);
                int bslot = q >> 2;
                int boff = (((nsub * KS + phalf) * 32 + blane) << 1) + bslot;
                sm.BH[boff] = bh;
            }
            if (!to_xw) {
                uint4 bl0 = wl4[u], bl1 = wl4[u + 1];
                #pragma unroll
                for (int q = 0; q < 8; q++) {
                    uint32_t bl = (q < 4) ? ((const uint32_t*)&bl0)[q] : ((const uint32_t*)&bl1)[q - 4];
                    int blane = nn * 4 + (q & 3);
                    int bslot = q >> 2;
                    int boff = (((nsub * KS + phalf) * 32 + blane) << 1) + bslot;
                    sm.BL[boff] = bl;
                }
            }
        }
        __syncthreads();
        #pragma unroll
        for (int ks = 0; ks < KS; ks++) {
            uint4 Ah[2], Al[2];
            #pragma unroll
            for (int mi = 0; mi < 2; mi++) {
                int ms = wr * 2 + mi;
                int off = ((ms * KS + ks) * 32 + lane) << 2;
                Ah[mi] = *(const uint4*)&sm.AH[off];
                Al[mi] = *(const uint4*)&sm.AL[off];
            }
            #pragma unroll
            for (int ni = 0; ni < 8; ni++) {
                int ns = wc * 8 + ni;
                int boff = ((ns * KS + ks) * 32 + lane) << 1;
                uint2 Bh = *(const uint2*)&sm.BH[boff];
                #pragma unroll
                for (int mi = 0; mi < 2; mi++) {
                    MMA_BF16(acc[mi][ni], Ah[mi], Bh);
                    MMA_BF16(acc[mi][ni], Al[mi], Bh);
                }
                if (!to_xw) {
                    uint2 Bl = *(const uint2*)&sm.BL[boff];
                    #pragma unroll
                    for (int mi = 0; mi < 2; mi++)
                        MMA_BF16(acc[mi][ni], Ah[mi], Bl);
                }
            }
        }
        __syncthreads();
    }

    #pragma unroll
    for (int mi = 0; mi < 2; mi++) {
        int r0 = m0 + wr * 32 + mi * 16 + (lane >> 2);
        #pragma unroll
        for (int ni = 0; ni < 8; ni++) {
            int col = j0 + wc * 64 + ni * 8 + (lane & 3) * 2;
            if (to_xw) {
                if (r0 < NN)
                    g_xwh[(size_t)r0 * 128 + (col >> 1)] = pack_bf16x2(acc[mi][ni][0], acc[mi][ni][1]);
                if (r0 + 8 < NN)
                    g_xwh[(size_t)(r0 + 8) * 128 + (col >> 1)] = pack_bf16x2(acc[mi][ni][2], acc[mi][ni][3]);
            } else {
                int jj = col - 256;
                float2 bv = *(const float2*)(b1 + jj);
                if (r0 < NN)
                    *(float2*)(g_xr + (size_t)r0 * CC + jj) =
                        make_float2(acc[mi][ni][0] + bv.x, acc[mi][ni][1] + bv.y);
                if (r0 + 8 < NN)
                    *(float2*)(g_xr + (size_t)(r0 + 8) * CC + jj) =
                        make_float2(acc[mi][ni][2] + bv.x, acc[mi][ni][3] + bv.y);
            }
        }
    }
}

// ---- fused: bf16 bucket gather + layer-1 epilogue + rank-1 layer-2 proj --
// Lane owns uint4 word-group `lane` of the row = cols [8*lane, 8*lane+8).
__device__ __forceinline__ void accum8(float* a, uint4 q) {
    a[0] += __uint_as_float(q.x << 16);
    a[1] += __uint_as_float(q.x & 0xFFFF0000u);
    a[2] += __uint_as_float(q.y << 16);
    a[3] += __uint_as_float(q.y & 0xFFFF0000u);
    a[4] += __uint_as_float(q.z << 16);
    a[5] += __uint_as_float(q.z & 0xFFFF0000u);
    a[6] += __uint_as_float(q.w << 16);
    a[7] += __uint_as_float(q.w & 0xFFFF0000u);
}

__global__ __launch_bounds__(128) void agg_st_kernel(const float* __restrict__ W2l,
                                                     const float* __restrict__ W2r)
{
    int n = (int)((blockIdx.x * 128 + threadIdx.x) >> 5);
    int lane = threadIdx.x & 31;
    if (n >= NN) return;
    const int* lst = g_bucket + (size_t)n * STR;
    int cnt = g_cnt[n];
    int m = min(cnt, STR);

    const uint4* base = (const uint4*)g_xwh;   // row = 32 uint4
    float a[8] = {};

    int i = 0;
    for (; i + 4 <= m; i += 4) {
        int4 s4 = *(const int4*)(lst + i);
        uint4 q0 = base[(size_t)s4.x * 32 + lane];
        uint4 q1 = base[(size_t)s4.y * 32 + lane];
        uint4 q2 = base[(size_t)s4.z * 32 + lane];
        uint4 q3 = base[(size_t)s4.w * 32 + lane];
        accum8(a, q0); accum8(a, q1); accum8(a, q2); accum8(a, q3);
    }
    for (; i < m; i++) {
        uint4 q = base[(size_t)lst[i] * 32 + lane];
        accum8(a, q);
    }

    float inv = 1.0f / fmaxf((float)cnt, 1.0f);
    float su = 0.f, tv = 0.f;
    {
        int c0 = lane * 8;
        float4 R = *(const float4*)(g_xr + (size_t)n * CC + c0);
        float4 U = __ldg((const float4*)(W2l + c0));
        float4 V = __ldg((const float4*)(W2r + c0));
        float h;
        h = fmaxf(fmaf(inv, a[0], R.x), 0.f); su = fmaf(h, U.x, su); tv = fmaf(h, V.x, tv);
        h = fmaxf(fmaf(inv, a[1], R.y), 0.f); su = fmaf(h, U.y, su); tv = fmaf(h, V.y, tv);
        h = fmaxf(fmaf(inv, a[2], R.z), 0.f); su = fmaf(h, U.z, su); tv = fmaf(h, V.z, tv);
        h = fmaxf(fmaf(inv, a[3], R.w), 0.f); su = fmaf(h, U.w, su); tv = fmaf(h, V.w, tv);
        R = *(const float4*)(g_xr + (size_t)n * CC + c0 + 4);
        U = __ldg((const float4*)(W2l + c0 + 4));
        V = __ldg((const float4*)(W2r + c0 + 4));
        h = fmaxf(fmaf(inv, a[4], R.x), 0.f); su = fmaf(h, U.x, su); tv = fmaf(h, V.x, tv);
        h = fmaxf(fmaf(inv, a[5], R.y), 0.f); su = fmaf(h, U.y, su); tv = fmaf(h, V.y, tv);
        h = fmaxf(fmaf(inv, a[6], R.z), 0.f); su = fmaf(h, U.z, su); tv = fmaf(h, V.z, tv);
        h = fmaxf(fmaf(inv, a[7], R.w), 0.f); su = fmaf(h, U.w, su); tv = fmaf(h, V.w, tv);
    }
    #pragma unroll
    for (int o = 16; o > 0; o >>= 1) {
        su += __shfl_down_sync(0xffffffffu, su, o);
        tv += __shfl_down_sync(0xffffffffu, tv, o);
    }
    if (lane == 0) { g_s[n] = su; g_t[n] = tv; }
}

// ---- fused: layer-2 scalar gather + relu + fc dot ----
__global__ void l2final_kernel(const float* __restrict__ fcw,
                               const float* __restrict__ b2)
{
    __shared__ float sdata[256];
    float local = 0.f;
    float bias2 = b2[0];
    for (int n = blockIdx.x * blockDim.x + threadIdx.x; n < NN;
         n += gridDim.x * blockDim.x) {
        const int* lst = g_bucket + (size_t)n * STR;
        int cnt = g_cnt[n];
        int m = min(cnt, STR);
        float sum = 0.f;
        int i = 0;
        for (; i + 4 <= m; i += 4) {
            int4 s4 = *(const int4*)(lst + i);
            sum += g_s[s4.x] + g_s[s4.y] + g_s[s4.z] + g_s[s4.w];
        }
        for (; i < m; i++) sum += g_s[lst[i]];
        float inv = 1.0f / fmaxf((float)cnt, 1.0f);
        float h = fmaxf(fmaf(inv, sum, bias2 + g_t[n]), 0.f);
        local = fmaf(h, fcw[n], local);
    }
    sdata[threadIdx.x] = local;
    __syncthreads();
    for (int s = 128; s > 0; s >>= 1) {
        if (threadIdx.x < s) sdata[threadIdx.x] += sdata[threadIdx.x + s];
        __syncthreads();
    }
    if (threadIdx.x == 0) g_part[blockIdx.x] = sdata[0];
}

__global__ void final2_kernel(float* __restrict__ out,
                              const float* __restrict__ fcb, int npart)
{
    __shared__ float sdata[256];
    float v = (threadIdx.x < npart) ? g_part[threadIdx.x] : 0.f;
    sdata[threadIdx.x] = v;
    __syncthreads();
    for (int s = 128; s > 0; s >>= 1) {
        if (threadIdx.x < s) sdata[threadIdx.x] += sdata[threadIdx.x + s];
        __syncthreads();
    }
    if (threadIdx.x == 0) out[0] = sdata[0] + fcb[0];
}

// ---------------- launch ----------------
extern "C" void kernel_launch(void* const* d_in, const int* in_sizes, int n_in,
                              void* d_out, int out_size) {
    const float* x    = (const float*)d_in[0];
    const int*   ei   = (const int*)d_in[1];     // int32 (JAX x64 disabled)
    const float* W1l  = (const float*)d_in[2];
    const float* b1   = (const float*)d_in[3];
    const float* W1r  = (const float*)d_in[4];
    const float* W2l  = (const float*)d_in[5];
    const float* b2   = (const float*)d_in[6];
    const float* W2r  = (const float*)d_in[7];
    const float* fcw  = (const float*)d_in[8];
    const float* fcb  = (const float*)d_in[9];
    float* out = (float*)d_out;

    zero_kernel<<<(NN + 255) / 256, 256>>>();
    prep_kernel<<<SCAT_B + XC_B + WC_B, 256>>>(ei, x, W1l, W1r);

    dim3 gemm_grid((NN + 127) / 128, 4);
    gemm_mma_kernel<<<gemm_grid, 256>>>(b1);

    agg_st_kernel<<<(NN * 32 + 127) / 128, 128>>>(W2l, W2r);

    const int FBLK = 148;
    l2final_kernel<<<FBLK, 256>>>(fcw, b2);
    final2_kernel<<<1, 256>>>(out, fcb, FBLK);
}

// round 10
// speedup vs baseline: 1.7987x; 1.0151x over previous
#include <cuda_runtime.h>
#include <cuda_bf16.h>
#include <cstdint>

#define NN 20000
#define EE 1280000
#define CC 256
#define STR 160   // bucket stride (max degree ~100 at 12 sigma)

// ---------------- device scratch (no allocations allowed) ----------------
__device__ __align__(16) uint32_t g_xwh[(size_t)NN * 128]; // x@W1_l^T bf16x2
__device__ __align__(16) float    g_xr[(size_t)NN * CC];   // x@W1_r^T + b1
__device__ __align__(16) uint32_t g_xh[(size_t)NN * 128];  // x hi split bf16x2
__device__ __align__(16) uint32_t g_xl[(size_t)NN * 128];  // x lo split
__device__ __align__(16) uint32_t g_wh[512 * 128];         // W hi split
__device__ __align__(16) uint32_t g_wl[512 * 128];         // W lo split
__device__ int   g_cnt[NN];
__device__ __align__(16) int g_bucket[(size_t)NN * STR];
__device__ float g_s[NN];
__device__ float g_t[NN];
__device__ float g_part[256];

__device__ __forceinline__ int clampN(int v) { return min(max(v, 0), NN - 1); }

__device__ __forceinline__ void bf16_split_pair(float a, float b, uint32_t& hi, uint32_t& lo) {
    __nv_bfloat16 ah = __float2bfloat16_rn(a);
    __nv_bfloat16 bh = __float2bfloat16_rn(b);
    __nv_bfloat16 al = __float2bfloat16_rn(a - __bfloat162float(ah));
    __nv_bfloat16 bl = __float2bfloat16_rn(b - __bfloat162float(bh));
    hi = ((uint32_t)__bfloat16_as_ushort(bh) << 16) | __bfloat16_as_ushort(ah);
    lo = ((uint32_t)__bfloat16_as_ushort(bl) << 16) | __bfloat16_as_ushort(al);
}
__device__ __forceinline__ uint32_t pack_bf16x2(float a, float b) {
    __nv_bfloat162 h = __floats2bfloat162_rn(a, b);
    return *(uint32_t*)&h;
}
__device__ __forceinline__ uint32_t hadd2u(uint32_t a, uint32_t b) {
    __nv_bfloat162 r = __hadd2(*(__nv_bfloat162*)&a, *(__nv_bfloat162*)&b);
    return *(uint32_t*)&r;
}

// ====== prep: zero cnt | x-split | W-split ===============================
#define ZB 79
#define XC_B 5000
#define WC_B 128

__global__ __launch_bounds__(256) void prep_kernel(
    const float* __restrict__ x,
    const float* __restrict__ Wl, const float* __restrict__ Wr)
{
    int b = blockIdx.x;
    int tid = threadIdx.x;
    if (b < ZB) {
        int t = b * 256 + tid;
        if (t < NN) g_cnt[t] = 0;
    } else if (b < ZB + XC_B) {
        int e = ((b - ZB) * 256 + tid) * 4;
        float4 v = *(const float4*)(x + e);
        uint32_t h0, l0, h1, l1;
        bf16_split_pair(v.x, v.y, h0, l0);
        bf16_split_pair(v.z, v.w, h1, l1);
        int row = e >> 8, kk = e & 255;
        size_t o = (size_t)row * 128 + (kk >> 1);
        *(uint2*)(g_xh + o) = make_uint2(h0, h1);
        *(uint2*)(g_xl + o) = make_uint2(l0, l1);
    } else {
        int e = ((b - ZB - XC_B) * 256 + tid) * 4;  // over 512*256
        int row = e >> 8, kk = e & 255;
        const float* W = (row < 256) ? (Wl + (size_t)row * CC + kk)
                                     : (Wr + (size_t)(row - 256) * CC + kk);
        float4 v = *(const float4*)W;
        uint32_t h0, l0, h1, l1;
        bf16_split_pair(v.x, v.y, h0, l0);
        bf16_split_pair(v.z, v.w, h1, l1);
        size_t o = (size_t)row * 128 + (kk >> 1);
        *(uint2*)(g_wh + o) = make_uint2(h0, h1);
        *(uint2*)(g_wl + o) = make_uint2(l0, l1);
    }
}

// ========== fused: scatter blocks + bf16 split GEMM blocks ===============
// blocks [0, 625): CSR-bucket scatter (8 edges/thread)
// blocks [625, 1253): GEMM 128x128 tile, xw 2-term / xr 3-term bf16 split
#define SCAT_B 625
#define GEMM_BX 157

#define KC 32
#define KS 2
#define A_FRAG_U32 (8 * KS * 32 * 4)
#define B_FRAG_U32 (16 * KS * 32 * 2)

struct SmemGemm {
    uint32_t AH[A_FRAG_U32];
    uint32_t AL[A_FRAG_U32];
    uint32_t BH[B_FRAG_U32];
    uint32_t BL[B_FRAG_U32];
};

#define MMA_BF16(d, a, b) \
    asm volatile("mma.sync.aligned.m16n8k16.row.col.f32.bf16.bf16.f32 " \
                 "{%0,%1,%2,%3}, {%4,%5,%6,%7}, {%8,%9}, {%0,%1,%2,%3};" \
                 : "+f"((d)[0]), "+f"((d)[1]), "+f"((d)[2]), "+f"((d)[3]) \
                 : "r"((a).x), "r"((a).y), "r"((a).z), "r"((a).w), \
                   "r"((b).x), "r"((b).y))

__global__ __launch_bounds__(256, 2) void gemm_scat_kernel(
    const int* __restrict__ ei, const float* __restrict__ b1)
{
    __shared__ SmemGemm sm;
    const int bid = blockIdx.x;
    const int tid = threadIdx.x;

    if (bid < SCAT_B) {
        // ---------------- scatter path ----------------
        int e8 = (bid * 256 + tid) * 8;
        #pragma unroll
        for (int h = 0; h < 2; h++) {
            int4 s = *(const int4*)(ei + e8 + h * 4);
            int4 d = *(const int4*)(ei + EE + e8 + h * 4);
            int d0 = clampN(d.x), d1 = clampN(d.y), d2 = clampN(d.z), d3 = clampN(d.w);
            int p0 = atomicAdd(&g_cnt[d0], 1);
            int p1 = atomicAdd(&g_cnt[d1], 1);
            int p2 = atomicAdd(&g_cnt[d2], 1);
            int p3 = atomicAdd(&g_cnt[d3], 1);
            if (p0 < STR) g_bucket[(size_t)d0 * STR + p0] = clampN(s.x);
            if (p1 < STR) g_bucket[(size_t)d1 * STR + p1] = clampN(s.y);
            if (p2 < STR) g_bucket[(size_t)d2 * STR + p2] = clampN(s.z);
            if (p3 < STR) g_bucket[(size_t)d3 * STR + p3] = clampN(s.w);
        }
        return;
    }

    // ---------------- GEMM path ----------------
    const int g = bid - SCAT_B;
    const int m0 = (g % GEMM_BX) * 128;
    const int j0 = (g / GEMM_BX) * 128;
    const bool to_xw = (j0 < 256);

    const int wid = tid >> 5;
    const int lane = tid & 31;
    const int wr = wid >> 1;
    const int wc = wid & 1;

    const int prow = tid >> 1;
    const int phalf = tid & 1;
    const int rr = prow & 15;
    const int msub = prow >> 4;
    const int nsub = prow >> 3;
    const int nn = prow & 7;

    const int garow = m0 + prow;
    const bool avalid = (garow < NN);
    const uint4* xh4 = (const uint4*)(g_xh + (size_t)min(garow, NN - 1) * 128);
    const uint4* xl4 = (const uint4*)(g_xl + (size_t)min(garow, NN - 1) * 128);
    const uint4* wh4 = (const uint4*)(g_wh + (size_t)(j0 + prow) * 128);
    const uint4* wl4 = (const uint4*)(g_wl + (size_t)(j0 + prow) * 128);

    float acc[2][8][4];
    #pragma unroll
    for (int mi = 0; mi < 2; mi++)
        #pragma unroll
        for (int ni = 0; ni < 8; ni++)
            #pragma unroll
            for (int q = 0; q < 4; q++) acc[mi][ni][q] = 0.f;

    for (int kc = 0; kc < CC / KC; kc++) {
        {
            int u = kc * 4 + phalf * 2;
            uint4 ah0 = xh4[u], ah1 = xh4[u + 1];
            uint4 al0 = xl4[u], al1 = xl4[u + 1];
            if (!avalid) { ah0 = ah1 = al0 = al1 = make_uint4(0, 0, 0, 0); }
            uint4 bh0 = wh4[u], bh1 = wh4[u + 1];
            #pragma unroll
            for (int q = 0; q < 8; q++) {
                uint32_t ah = (q < 4) ? ((const uint32_t*)&ah0)[q] : ((const uint32_t*)&ah1)[q - 4];
                uint32_t al = (q < 4) ? ((const uint32_t*)&al0)[q] : ((const uint32_t*)&al1)[q - 4];
                uint32_t bh = (q < 4) ? ((const uint32_t*)&bh0)[q] : ((const uint32_t*)&bh1)[q - 4];
                int alane = (rr & 7) * 4 + (q & 3);
                int aslot = (rr >> 3) + ((q >> 2) << 1);
                int aoff = (((msub * KS + phalf) * 32 + alane) << 2) + aslot;
                sm.AH[aoff] = ah; sm.AL[aoff] = al;
                int blane = nn * 4 + (q & 3);
                int bslot = q >> 2;
                int boff = (((nsub * KS + phalf) * 32 + blane) << 1) + bslot;
                sm.BH[boff] = bh;
            }
            if (!to_xw) {
                uint4 bl0 = wl4[u], bl1 = wl4[u + 1];
                #pragma unroll
                for (int q = 0; q < 8; q++) {
                    uint32_t bl = (q < 4) ? ((const uint32_t*)&bl0)[q] : ((const uint32_t*)&bl1)[q - 4];
                    int blane = nn * 4 + (q & 3);
                    int bslot = q >> 2;
                    int boff = (((nsub * KS + phalf) * 32 + blane) << 1) + bslot;
                    sm.BL[boff] = bl;
                }
            }
        }
        __syncthreads();
        #pragma unroll
        for (int ks = 0; ks < KS; ks++) {
            uint4 Ah[2], Al[2];
            #pragma unroll
            for (int mi = 0; mi < 2; mi++) {
                int ms = wr * 2 + mi;
                int off = ((ms * KS + ks) * 32 + lane) << 2;
                Ah[mi] = *(const uint4*)&sm.AH[off];
                Al[mi] = *(const uint4*)&sm.AL[off];
            }
            #pragma unroll
            for (int ni = 0; ni < 8; ni++) {
                int ns = wc * 8 + ni;
                int boff = ((ns * KS + ks) * 32 + lane) << 1;
                uint2 Bh = *(const uint2*)&sm.BH[boff];
                #pragma unroll
                for (int mi = 0; mi < 2; mi++) {
                    MMA_BF16(acc[mi][ni], Ah[mi], Bh);
                    MMA_BF16(acc[mi][ni], Al[mi], Bh);
                }
                if (!to_xw) {
                    uint2 Bl = *(const uint2*)&sm.BL[boff];
                    #pragma unroll
                    for (int mi = 0; mi < 2; mi++)
                        MMA_BF16(acc[mi][ni], Ah[mi], Bl);
                }
            }
        }
        __syncthreads();
    }

    #pragma unroll
    for (int mi = 0; mi < 2; mi++) {
        int r0 = m0 + wr * 32 + mi * 16 + (lane >> 2);
        #pragma unroll
        for (int ni = 0; ni < 8; ni++) {
            int col = j0 + wc * 64 + ni * 8 + (lane & 3) * 2;
            if (to_xw) {
                if (r0 < NN)
                    g_xwh[(size_t)r0 * 128 + (col >> 1)] = pack_bf16x2(acc[mi][ni][0], acc[mi][ni][1]);
                if (r0 + 8 < NN)
                    g_xwh[(size_t)(r0 + 8) * 128 + (col >> 1)] = pack_bf16x2(acc[mi][ni][2], acc[mi][ni][3]);
            } else {
                int jj = col - 256;
                float2 bv = *(const float2*)(b1 + jj);
                if (r0 < NN)
                    *(float2*)(g_xr + (size_t)r0 * CC + jj) =
                        make_float2(acc[mi][ni][0] + bv.x, acc[mi][ni][1] + bv.y);
                if (r0 + 8 < NN)
                    *(float2*)(g_xr + (size_t)(r0 + 8) * CC + jj) =
                        make_float2(acc[mi][ni][2] + bv.x, acc[mi][ni][3] + bv.y);
            }
        }
    }
}

// ---- fused: bf16 bucket gather (paired HADD2) + epilogue + rank-1 proj --
__device__ __forceinline__ void accum8(float* a, uint4 q) {
    a[0] += __uint_as_float(q.x << 16);
    a[1] += __uint_as_float(q.x & 0xFFFF0000u);
    a[2] += __uint_as_float(q.y << 16);
    a[3] += __uint_as_float(q.y & 0xFFFF0000u);
    a[4] += __uint_as_float(q.z << 16);
    a[5] += __uint_as_float(q.z & 0xFFFF0000u);
    a[6] += __uint_as_float(q.w << 16);
    a[7] += __uint_as_float(q.w & 0xFFFF0000u);
}
__device__ __forceinline__ uint4 hadd2u4(uint4 a, uint4 b) {
    return make_uint4(hadd2u(a.x, b.x), hadd2u(a.y, b.y),
                      hadd2u(a.z, b.z), hadd2u(a.w, b.w));
}

__global__ __launch_bounds__(128) void agg_st_kernel(const float* __restrict__ W2l,
                                                     const float* __restrict__ W2r)
{
    int n = (int)((blockIdx.x * 128 + threadIdx.x) >> 5);
    int lane = threadIdx.x & 31;
    if (n >= NN) return;
    const int* lst = g_bucket + (size_t)n * STR;
    int cnt = g_cnt[n];
    int m = min(cnt, STR);

    const uint4* base = (const uint4*)g_xwh;   // row = 32 uint4
    float a[8] = {};

    int i = 0;
    for (; i + 4 <= m; i += 4) {
        int4 s4 = *(const int4*)(lst + i);
        uint4 q0 = base[(size_t)s4.x * 32 + lane];
        uint4 q1 = base[(size_t)s4.y * 32 + lane];
        uint4 q2 = base[(size_t)s4.z * 32 + lane];
        uint4 q3 = base[(size_t)s4.w * 32 + lane];
        accum8(a, hadd2u4(q0, q1));          // one bf16 add per element pair
        accum8(a, hadd2u4(q2, q3));
    }
    if (i + 2 <= m) {
        uint4 q0 = base[(size_t)lst[i] * 32 + lane];
        uint4 q1 = base[(size_t)lst[i + 1] * 32 + lane];
        accum8(a, hadd2u4(q0, q1));
        i += 2;
    }
    if (i < m) {
        accum8(a, base[(size_t)lst[i] * 32 + lane]);
    }

    float inv = 1.0f / fmaxf((float)cnt, 1.0f);
    float su = 0.f, tv = 0.f;
    {
        int c0 = lane * 8;
        float4 R = *(const float4*)(g_xr + (size_t)n * CC + c0);
        float4 U = __ldg((const float4*)(W2l + c0));
        float4 V = __ldg((const float4*)(W2r + c0));
        float h;
        h = fmaxf(fmaf(inv, a[0], R.x), 0.f); su = fmaf(h, U.x, su); tv = fmaf(h, V.x, tv);
        h = fmaxf(fmaf(inv, a[1], R.y), 0.f); su = fmaf(h, U.y, su); tv = fmaf(h, V.y, tv);
        h = fmaxf(fmaf(inv, a[2], R.z), 0.f); su = fmaf(h, U.z, su); tv = fmaf(h, V.z, tv);
        h = fmaxf(fmaf(inv, a[3], R.w), 0.f); su = fmaf(h, U.w, su); tv = fmaf(h, V.w, tv);
        R = *(const float4*)(g_xr + (size_t)n * CC + c0 + 4);
        U = __ldg((const float4*)(W2l + c0 + 4));
        V = __ldg((const float4*)(W2r + c0 + 4));
        h = fmaxf(fmaf(inv, a[4], R.x), 0.f); su = fmaf(h, U.x, su); tv = fmaf(h, V.x, tv);
        h = fmaxf(fmaf(inv, a[5], R.y), 0.f); su = fmaf(h, U.y, su); tv = fmaf(h, V.y, tv);
        h = fmaxf(fmaf(inv, a[6], R.z), 0.f); su = fmaf(h, U.z, su); tv = fmaf(h, V.z, tv);
        h = fmaxf(fmaf(inv, a[7], R.w), 0.f); su = fmaf(h, U.w, su); tv = fmaf(h, V.w, tv);
    }
    #pragma unroll
    for (int o = 16; o > 0; o >>= 1) {
        su += __shfl_down_sync(0xffffffffu, su, o);
        tv += __shfl_down_sync(0xffffffffu, tv, o);
    }
    if (lane == 0) { g_s[n] = su; g_t[n] = tv; }
}

// ---- fused: layer-2 scalar gather + relu + fc dot ----
__global__ void l2final_kernel(const float* __restrict__ fcw,
                               const float* __restrict__ b2)
{
    __shared__ float sdata[256];
    float local = 0.f;
    float bias2 = b2[0];
    for (int n = blockIdx.x * blockDim.x + threadIdx.x; n < NN;
         n += gridDim.x * blockDim.x) {
        const int* lst = g_bucket + (size_t)n * STR;
        int cnt = g_cnt[n];
        int m = min(cnt, STR);
        float sum = 0.f;
        int i = 0;
        for (; i + 4 <= m; i += 4) {
            int4 s4 = *(const int4*)(lst + i);
            sum += g_s[s4.x] + g_s[s4.y] + g_s[s4.z] + g_s[s4.w];
        }
        for (; i < m; i++) sum += g_s[lst[i]];
        float inv = 1.0f / fmaxf((float)cnt, 1.0f);
        float h = fmaxf(fmaf(inv, sum, bias2 + g_t[n]), 0.f);
        local = fmaf(h, fcw[n], local);
    }
    sdata[threadIdx.x] = local;
    __syncthreads();
    for (int s = 128; s > 0; s >>= 1) {
        if (threadIdx.x < s) sdata[threadIdx.x] += sdata[threadIdx.x + s];
        __syncthreads();
    }
    if (threadIdx.x == 0) g_part[blockIdx.x] = sdata[0];
}

__global__ void final2_kernel(float* __restrict__ out,
                              const float* __restrict__ fcb, int npart)
{
    __shared__ float sdata[256];
    float v = (threadIdx.x < npart) ? g_part[threadIdx.x] : 0.f;
    sdata[threadIdx.x] = v;
    __syncthreads();
    for (int s = 128; s > 0; s >>= 1) {
        if (threadIdx.x < s) sdata[threadIdx.x] += sdata[threadIdx.x + s];
        __syncthreads();
    }
    if (threadIdx.x == 0) out[0] = sdata[0] + fcb[0];
}

// ---------------- launch ----------------
extern "C" void kernel_launch(void* const* d_in, const int* in_sizes, int n_in,
                              void* d_out, int out_size) {
    const float* x    = (const float*)d_in[0];
    const int*   ei   = (const int*)d_in[1];     // int32 (JAX x64 disabled)
    const float* W1l  = (const float*)d_in[2];
    const float* b1   = (const float*)d_in[3];
    const float* W1r  = (const float*)d_in[4];
    const float* W2l  = (const float*)d_in[5];
    const float* b2   = (const float*)d_in[6];
    const float* W2r  = (const float*)d_in[7];
    const float* fcw  = (const float*)d_in[8];
    const float* fcb  = (const float*)d_in[9];
    float* out = (float*)d_out;

    prep_kernel<<<ZB + XC_B + WC_B, 256>>>(x, W1l, W1r);

    gemm_scat_kernel<<<SCAT_B + GEMM_BX * 4, 256>>>(ei, b1);

    agg_st_kernel<<<(NN * 32 + 127) / 128, 128>>>(W2l, W2r);

    const int FBLK = 148;
    l2final_kernel<<<FBLK, 256>>>(fcw, b2);
    final2_kernel<<<1, 256>>>(out, fcb, FBLK);
}

// round 12
// speedup vs baseline: 1.9063x; 1.0598x over previous
#include <cuda_runtime.h>
#include <cuda_bf16.h>
#include <cstdint>

#define NN 20000
#define EE 1280000
#define CC 256
#define STR 160   // bucket stride (max degree ~100 at 12 sigma)

// ---------------- device scratch (no allocations allowed) ----------------
__device__ __align__(16) uint32_t g_xwh[(size_t)NN * 128]; // x@W1_l^T bf16x2
__device__ __align__(16) float    g_xr[(size_t)NN * CC];   // x@W1_r^T + b1
__device__ __align__(16) uint32_t g_xh[(size_t)NN * 128];  // x hi split bf16x2
__device__ __align__(16) uint32_t g_xl[(size_t)NN * 128];  // x lo split
__device__ __align__(16) uint32_t g_wh[512 * 128];         // W hi split
__device__ __align__(16) uint32_t g_wl[512 * 128];         // W lo split
__device__ int   g_cnt[NN];
__device__ __align__(16) int g_bucket[(size_t)NN * STR];
__device__ float g_s[NN];
__device__ float g_t[NN];
__device__ float g_part[2560];

__device__ __forceinline__ int clampN(int v) { return min(max(v, 0), NN - 1); }

__device__ __forceinline__ void bf16_split_pair(float a, float b, uint32_t& hi, uint32_t& lo) {
    __nv_bfloat16 ah = __float2bfloat16_rn(a);
    __nv_bfloat16 bh = __float2bfloat16_rn(b);
    __nv_bfloat16 al = __float2bfloat16_rn(a - __bfloat162float(ah));
    __nv_bfloat16 bl = __float2bfloat16_rn(b - __bfloat162float(bh));
    hi = ((uint32_t)__bfloat16_as_ushort(bh) << 16) | __bfloat16_as_ushort(ah);
    lo = ((uint32_t)__bfloat16_as_ushort(bl) << 16) | __bfloat16_as_ushort(al);
}
__device__ __forceinline__ uint32_t pack_bf16x2(float a, float b) {
    __nv_bfloat162 h = __floats2bfloat162_rn(a, b);
    return *(uint32_t*)&h;
}
__device__ __forceinline__ uint32_t hadd2u(uint32_t a, uint32_t b) {
    __nv_bfloat162 r = __hadd2(*(__nv_bfloat162*)&a, *(__nv_bfloat162*)&b);
    return *(uint32_t*)&r;
}

// ====== prep: zero cnt | x-split | W-split ===============================
#define ZB 79
#define XC_B 5000
#define WC_B 128

__global__ __launch_bounds__(256) void prep_kernel(
    const float* __restrict__ x,
    const float* __restrict__ Wl, const float* __restrict__ Wr)
{
    int b = blockIdx.x;
    int tid = threadIdx.x;
    if (b < ZB) {
        int t = b * 256 + tid;
        if (t < NN) g_cnt[t] = 0;
    } else if (b < ZB + XC_B) {
        int e = ((b - ZB) * 256 + tid) * 4;
        float4 v = *(const float4*)(x + e);
        uint32_t h0, l0, h1, l1;
        bf16_split_pair(v.x, v.y, h0, l0);
        bf16_split_pair(v.z, v.w, h1, l1);
        int row = e >> 8, kk = e & 255;
        size_t o = (size_t)row * 128 + (kk >> 1);
        *(uint2*)(g_xh + o) = make_uint2(h0, h1);
        *(uint2*)(g_xl + o) = make_uint2(l0, l1);
    } else {
        int e = ((b - ZB - XC_B) * 256 + tid) * 4;  // over 512*256
        int row = e >> 8, kk = e & 255;
        const float* W = (row < 256) ? (Wl + (size_t)row * CC + kk)
                                     : (Wr + (size_t)(row - 256) * CC + kk);
        float4 v = *(const float4*)W;
        uint32_t h0, l0, h1, l1;
        bf16_split_pair(v.x, v.y, h0, l0);
        bf16_split_pair(v.z, v.w, h1, l1);
        size_t o = (size_t)row * 128 + (kk >> 1);
        *(uint2*)(g_wh + o) = make_uint2(h0, h1);
        *(uint2*)(g_wl + o) = make_uint2(l0, l1);
    }
}

// ========== fused: interleaved scatter + bf16 split GEMM =================
// bid < 1250: odd -> scatter (bid>>1), even -> GEMM (bid>>1)
// bid >= 1250: GEMM (bid - 625)    [gemm ids 625..627]
// GEMM: xw blocks 2-term (Ah*Bh + Al*Bh), xr blocks 3-term (+ Ah*Bl).
#define SCAT_B 625
#define GEMM_BX 157

#define KC 32
#define KS 2
#define A_FRAG_U32 (8 * KS * 32 * 4)
#define B_FRAG_U32 (16 * KS * 32 * 2)

struct SmemGemm {
    uint32_t AH[A_FRAG_U32];
    uint32_t AL[A_FRAG_U32];
    uint32_t BH[B_FRAG_U32];
    uint32_t BL[B_FRAG_U32];
};

#define MMA_BF16(d, a, b) \
    asm volatile("mma.sync.aligned.m16n8k16.row.col.f32.bf16.bf16.f32 " \
                 "{%0,%1,%2,%3}, {%4,%5,%6,%7}, {%8,%9}, {%0,%1,%2,%3};" \
                 : "+f"((d)[0]), "+f"((d)[1]), "+f"((d)[2]), "+f"((d)[3]) \
                 : "r"((a).x), "r"((a).y), "r"((a).z), "r"((a).w), \
                   "r"((b).x), "r"((b).y))

__global__ __launch_bounds__(256, 2) void gemm_scat_kernel(
    const int* __restrict__ ei, const float* __restrict__ b1)
{
    __shared__ SmemGemm sm;
    const int bid = blockIdx.x;
    const int tid = threadIdx.x;

    if (bid < 2 * SCAT_B && (bid & 1)) {
        // ---------------- scatter path ----------------
        int e8 = ((bid >> 1) * 256 + tid) * 8;
        #pragma unroll
        for (int h = 0; h < 2; h++) {
            int4 s = *(const int4*)(ei + e8 + h * 4);
            int4 d = *(const int4*)(ei + EE + e8 + h * 4);
            int d0 = clampN(d.x), d1 = clampN(d.y), d2 = clampN(d.z), d3 = clampN(d.w);
            int p0 = atomicAdd(&g_cnt[d0], 1);
            int p1 = atomicAdd(&g_cnt[d1], 1);
            int p2 = atomicAdd(&g_cnt[d2], 1);
            int p3 = atomicAdd(&g_cnt[d3], 1);
            if (p0 < STR) g_bucket[(size_t)d0 * STR + p0] = clampN(s.x);
            if (p1 < STR) g_bucket[(size_t)d1 * STR + p1] = clampN(s.y);
            if (p2 < STR) g_bucket[(size_t)d2 * STR + p2] = clampN(s.z);
            if (p3 < STR) g_bucket[(size_t)d3 * STR + p3] = clampN(s.w);
        }
        return;
    }

    // ---------------- GEMM path ----------------
    const int g = (bid < 2 * SCAT_B) ? (bid >> 1) : (bid - SCAT_B);
    const int m0 = (g % GEMM_BX) * 128;
    const int j0 = (g / GEMM_BX) * 128;
    const bool to_xw = (j0 < 256);

    const int wid = tid >> 5;
    const int lane = tid & 31;
    const int wr = wid >> 1;
    const int wc = wid & 1;

    const int prow = tid >> 1;
    const int phalf = tid & 1;
    const int rr = prow & 15;
    const int msub = prow >> 4;
    const int nsub = prow >> 3;
    const int nn = prow & 7;

    const int garow = m0 + prow;
    const bool avalid = (garow < NN);
    const uint4* xh4 = (const uint4*)(g_xh + (size_t)min(garow, NN - 1) * 128);
    const uint4* xl4 = (const uint4*)(g_xl + (size_t)min(garow, NN - 1) * 128);
    const uint4* wh4 = (const uint4*)(g_wh + (size_t)(j0 + prow) * 128);
    const uint4* wl4 = (const uint4*)(g_wl + (size_t)(j0 + prow) * 128);

    float acc[2][8][4];
    #pragma unroll
    for (int mi = 0; mi < 2; mi++)
        #pragma unroll
        for (int ni = 0; ni < 8; ni++)
            #pragma unroll
            for (int q = 0; q < 4; q++) acc[mi][ni][q] = 0.f;

    for (int kc = 0; kc < CC / KC; kc++) {
        {
            int u = kc * 4 + phalf * 2;
            uint4 ah0 = xh4[u], ah1 = xh4[u + 1];
            uint4 al0 = xl4[u], al1 = xl4[u + 1];
            if (!avalid) { ah0 = ah1 = al0 = al1 = make_uint4(0, 0, 0, 0); }
            uint4 bh0 = wh4[u], bh1 = wh4[u + 1];
            #pragma unroll
            for (int q = 0; q < 8; q++) {
                uint32_t ah = (q < 4) ? ((const uint32_t*)&ah0)[q] : ((const uint32_t*)&ah1)[q - 4];
                uint32_t al = (q < 4) ? ((const uint32_t*)&al0)[q] : ((const uint32_t*)&al1)[q - 4];
                uint32_t bh = (q < 4) ? ((const uint32_t*)&bh0)[q] : ((const uint32_t*)&bh1)[q - 4];
                int alane = (rr & 7) * 4 + (q & 3);
                int aslot = (rr >> 3) + ((q >> 2) << 1);
                int aoff = (((msub * KS + phalf) * 32 + alane) << 2) + aslot;
                sm.AH[aoff] = ah; sm.AL[aoff] = al;
                int blane = nn * 4 + (q & 3);
                int bslot = q >> 2;
                int boff = (((nsub * KS + phalf) * 32 + blane) << 1) + bslot;
                sm.BH[boff] = bh;
            }
            if (!to_xw) {
                uint4 bl0 = wl4[u], bl1 = wl4[u + 1];
                #pragma unroll
                for (int q = 0; q < 8; q++) {
                    uint32_t bl = (q < 4) ? ((const uint32_t*)&bl0)[q] : ((const uint32_t*)&bl1)[q - 4];
                    int blane = nn * 4 + (q & 3);
                    int bslot = q >> 2;
                    int boff = (((nsub * KS + phalf) * 32 + blane) << 1) + bslot;
                    sm.BL[boff] = bl;
                }
            }
        }
        __syncthreads();
        #pragma unroll
        for (int ks = 0; ks < KS; ks++) {
            uint4 Ah[2], Al[2];
            #pragma unroll
            for (int mi = 0; mi < 2; mi++) {
                int ms = wr * 2 + mi;
                int off = ((ms * KS + ks) * 32 + lane) << 2;
                Ah[mi] = *(const uint4*)&sm.AH[off];
                Al[mi] = *(const uint4*)&sm.AL[off];
            }
            #pragma unroll
            for (int ni = 0; ni < 8; ni++) {
                int ns = wc * 8 + ni;
                int boff = ((ns * KS + ks) * 32 + lane) << 1;
                uint2 Bh = *(const uint2*)&sm.BH[boff];
                #pragma unroll
                for (int mi = 0; mi < 2; mi++) {
                    MMA_BF16(acc[mi][ni], Ah[mi], Bh);
                    MMA_BF16(acc[mi][ni], Al[mi], Bh);
                }
                if (!to_xw) {
                    uint2 Bl = *(const uint2*)&sm.BL[boff];
                    #pragma unroll
                    for (int mi = 0; mi < 2; mi++)
                        MMA_BF16(acc[mi][ni], Ah[mi], Bl);
                }
            }
        }
        __syncthreads();
    }

    #pragma unroll
    for (int mi = 0; mi < 2; mi++) {
        int r0 = m0 + wr * 32 + mi * 16 + (lane >> 2);
        #pragma unroll
        for (int ni = 0; ni < 8; ni++) {
            int col = j0 + wc * 64 + ni * 8 + (lane & 3) * 2;
            if (to_xw) {
                if (r0 < NN)
                    g_xwh[(size_t)r0 * 128 + (col >> 1)] = pack_bf16x2(acc[mi][ni][0], acc[mi][ni][1]);
                if (r0 + 8 < NN)
                    g_xwh[(size_t)(r0 + 8) * 128 + (col >> 1)] = pack_bf16x2(acc[mi][ni][2], acc[mi][ni][3]);
            } else {
                int jj = col - 256;
                float2 bv = *(const float2*)(b1 + jj);
                if (r0 < NN)
                    *(float2*)(g_xr + (size_t)r0 * CC + jj) =
                        make_float2(acc[mi][ni][0] + bv.x, acc[mi][ni][1] + bv.y);
                if (r0 + 8 < NN)
                    *(float2*)(g_xr + (size_t)(r0 + 8) * CC + jj) =
                        make_float2(acc[mi][ni][2] + bv.x, acc[mi][ni][3] + bv.y);
            }
        }
    }
}

// ---- fused: bf16 bucket gather (paired HADD2) + epilogue + rank-1 proj --
__device__ __forceinline__ void accum8(float* a, uint4 q) {
    a[0] += __uint_as_float(q.x << 16);
    a[1] += __uint_as_float(q.x & 0xFFFF0000u);
    a[2] += __uint_as_float(q.y << 16);
    a[3] += __uint_as_float(q.y & 0xFFFF0000u);
    a[4] += __uint_as_float(q.z << 16);
    a[5] += __uint_as_float(q.z & 0xFFFF0000u);
    a[6] += __uint_as_float(q.w << 16);
    a[7] += __uint_as_float(q.w & 0xFFFF0000u);
}
__device__ __forceinline__ uint4 hadd2u4(uint4 a, uint4 b) {
    return make_uint4(hadd2u(a.x, b.x), hadd2u(a.y, b.y),
                      hadd2u(a.z, b.z), hadd2u(a.w, b.w));
}

__global__ __launch_bounds__(128) void agg_st_kernel(const float* __restrict__ W2l,
                                                     const float* __restrict__ W2r)
{
    int n = (int)((blockIdx.x * 128 + threadIdx.x) >> 5);
    int lane = threadIdx.x & 31;
    if (n >= NN) return;
    const int* lst = g_bucket + (size_t)n * STR;
    int cnt = g_cnt[n];
    int m = min(cnt, STR);

    const uint4* base = (const uint4*)g_xwh;   // row = 32 uint4
    float a[8] = {};

    int i = 0;
    for (; i + 4 <= m; i += 4) {
        int4 s4 = *(const int4*)(lst + i);
        uint4 q0 = base[(size_t)s4.x * 32 + lane];
        uint4 q1 = base[(size_t)s4.y * 32 + lane];
        uint4 q2 = base[(size_t)s4.z * 32 + lane];
        uint4 q3 = base[(size_t)s4.w * 32 + lane];
        accum8(a, hadd2u4(q0, q1));          // one bf16 add per element pair
        accum8(a, hadd2u4(q2, q3));
    }
    if (i + 2 <= m) {
        uint4 q0 = base[(size_t)lst[i] * 32 + lane];
        uint4 q1 = base[(size_t)lst[i + 1] * 32 + lane];
        accum8(a, hadd2u4(q0, q1));
        i += 2;
    }
    if (i < m) {
        accum8(a, base[(size_t)lst[i] * 32 + lane]);
    }

    float inv = 1.0f / fmaxf((float)cnt, 1.0f);
    float su = 0.f, tv = 0.f;
    {
        int c0 = lane * 8;
        float4 R = *(const float4*)(g_xr + (size_t)n * CC + c0);
        float4 U = __ldg((const float4*)(W2l + c0));
        float4 V = __ldg((const float4*)(W2r + c0));
        float h;
        h = fmaxf(fmaf(inv, a[0], R.x), 0.f); su = fmaf(h, U.x, su); tv = fmaf(h, V.x, tv);
        h = fmaxf(fmaf(inv, a[1], R.y), 0.f); su = fmaf(h, U.y, su); tv = fmaf(h, V.y, tv);
        h = fmaxf(fmaf(inv, a[2], R.z), 0.f); su = fmaf(h, U.z, su); tv = fmaf(h, V.z, tv);
        h = fmaxf(fmaf(inv, a[3], R.w), 0.f); su = fmaf(h, U.w, su); tv = fmaf(h, V.w, tv);
        R = *(const float4*)(g_xr + (size_t)n * CC + c0 + 4);
        U = __ldg((const float4*)(W2l + c0 + 4));
        V = __ldg((const float4*)(W2r + c0 + 4));
        h = fmaxf(fmaf(inv, a[4], R.x), 0.f); su = fmaf(h, U.x, su); tv = fmaf(h, V.x, tv);
        h = fmaxf(fmaf(inv, a[5], R.y), 0.f); su = fmaf(h, U.y, su); tv = fmaf(h, V.y, tv);
        h = fmaxf(fmaf(inv, a[6], R.z), 0.f); su = fmaf(h, U.z, su); tv = fmaf(h, V.z, tv);
        h = fmaxf(fmaf(inv, a[7], R.w), 0.f); su = fmaf(h, U.w, su); tv = fmaf(h, V.w, tv);
    }
    #pragma unroll
    for (int o = 16; o > 0; o >>= 1) {
        su += __shfl_down_sync(0xffffffffu, su, o);
        tv += __shfl_down_sync(0xffffffffu, tv, o);
    }
    if (lane == 0) { g_s[n] = su; g_t[n] = tv; }
}

// ---- fused: layer-2 scalar gather + relu + fc dot (warp per node) -------
__global__ __launch_bounds__(256) void l2final_kernel(const float* __restrict__ fcw,
                                                      const float* __restrict__ b2)
{
    __shared__ float ws[8];
    int tid = threadIdx.x;
    int wid = tid >> 5;
    int lane = tid & 31;
    int n = (int)((blockIdx.x * 256 + tid) >> 5);
    float local = 0.f;
    if (n < NN) {
        const int* lst = g_bucket + (size_t)n * STR;
        int cnt = g_cnt[n];
        int m = min(cnt, STR);
        float sum = 0.f;
        for (int i = lane; i < m; i += 32) sum += g_s[lst[i]];
        #pragma unroll
        for (int o = 16; o > 0; o >>= 1)
            sum += __shfl_down_sync(0xffffffffu, sum, o);
        if (lane == 0) {
            float inv = 1.0f / fmaxf((float)cnt, 1.0f);
            float h = fmaxf(fmaf(inv, sum, b2[0] + g_t[n]), 0.f);
            local = h * fcw[n];
        }
    }
    if (lane == 0) ws[wid] = local;
    __syncthreads();
    if (tid == 0) {
        float s = ws[0] + ws[1] + ws[2] + ws[3] + ws[4] + ws[5] + ws[6] + ws[7];
        g_part[blockIdx.x] = s;
    }
}

#define L2_B 2500

__global__ __launch_bounds__(1024) void final2_kernel(float* __restrict__ out,
                                                      const float* __restrict__ fcb)
{
    __shared__ float sdata[1024];
    int tid = threadIdx.x;
    float v = 0.f;
    for (int i = tid; i < L2_B; i += 1024) v += g_part[i];
    sdata[tid] = v;
    __syncthreads();
    for (int s = 512; s > 0; s >>= 1) {
        if (tid < s) sdata[tid] += sdata[tid + s];
        __syncthreads();
    }
    if (tid == 0) out[0] = sdata[0] + fcb[0];
}

// ---------------- launch ----------------
extern "C" void kernel_launch(void* const* d_in, const int* in_sizes, int n_in,
                              void* d_out, int out_size) {
    const float* x    = (const float*)d_in[0];
    const int*   ei   = (const int*)d_in[1];     // int32 (JAX x64 disabled)
    const float* W1l  = (const float*)d_in[2];
    const float* b1   = (const float*)d_in[3];
    const float* W1r  = (const float*)d_in[4];
    const float* W2l  = (const float*)d_in[5];
    const float* b2   = (const float*)d_in[6];
    const float* W2r  = (const float*)d_in[7];
    const float* fcw  = (const float*)d_in[8];
    const float* fcb  = (const float*)d_in[9];
    float* out = (float*)d_out;

    prep_kernel<<<ZB + XC_B + WC_B, 256>>>(x, W1l, W1r);

    gemm_scat_kernel<<<2 * SCAT_B + 3, 256>>>(ei, b1);

    agg_st_kernel<<<(NN * 32 + 127) / 128, 128>>>(W2l, W2r);

    l2final_kernel<<<L2_B, 256>>>(fcw, b2);
    final2_kernel<<<1, 1024>>>(out, fcb);
}